// round 12
// baseline (speedup 1.0000x reference)
#include <cuda_runtime.h>
#include <math.h>
#include <stdint.h>

#define BATCH 4096
#define K1 8450
#define K2 1250
#define KP1P 8704          // h1 row pitch (17 * 512)
#define KP2P 1536          // W2 row pitch

// ---------------- scratch (device globals; zero-initialized) ---------------
__device__ float g_h1[(size_t)BATCH * KP1P];
__device__ float g_f3[BATCH * 50];
__device__ float g_o2[BATCH * 10];
__device__ int   g_e1[BATCH];
__device__ int   g_e2[BATCH];
__device__ float g_W1[12 * KP1P];    // rows 0-9: l2c1@l1c1; 10-11: d1_w
__device__ float g_W2[12 * KP2P];
__device__ float g_b1c[12];
__device__ float g_b2c[12];
__device__ float g_part1[BATCH * 24];  // [b][split(2)][12]
__device__ float2 g_wpk2[50 * 500];    // conv2 weights [ic][oc][10] dup, pad k=9 zero

// ================= merged prep kernel =======================================
__device__ void combine_part(
    const float* __restrict__ l1, const float* __restrict__ b1,
    const float* __restrict__ l2, const float* __restrict__ b2,
    const float* __restrict__ dw, const float* __restrict__ db,
    int K, int Kp, float* __restrict__ W12, float* __restrict__ bc12,
    int blk, float* l2T)
{
    int tid = threadIdx.x;
    for (int i = tid; i < 5000; i += 256) {
        int j = i / 500, r = i - j * 500;
        l2T[r * 12 + j] = l2[i];
    }
    for (int r = tid; r < 500; r += 256) { l2T[r * 12 + 10] = 0.f; l2T[r * 12 + 11] = 0.f; }
    __syncthreads();

    int k = blk * 256 + tid;
    if (k < Kp) {
        if (k < K) {
            float acc[10];
            #pragma unroll
            for (int j = 0; j < 10; j++) acc[j] = 0.f;
            #pragma unroll 4
            for (int r = 0; r < 500; r++) {
                float a = __ldg(&l1[(size_t)r * K + k]);
                float4 w0 = *(const float4*)&l2T[r * 12];
                float4 w1 = *(const float4*)&l2T[r * 12 + 4];
                float2 w2 = *(const float2*)&l2T[r * 12 + 8];
                acc[0] += a * w0.x; acc[1] += a * w0.y; acc[2] += a * w0.z; acc[3] += a * w0.w;
                acc[4] += a * w1.x; acc[5] += a * w1.y; acc[6] += a * w1.z; acc[7] += a * w1.w;
                acc[8] += a * w2.x; acc[9] += a * w2.y;
            }
            #pragma unroll
            for (int j = 0; j < 10; j++) W12[(size_t)j * Kp + k] = acc[j];
            W12[(size_t)10 * Kp + k] = __ldg(&dw[k]);
            W12[(size_t)11 * Kp + k] = __ldg(&dw[K + k]);
        } else {
            #pragma unroll
            for (int j = 0; j < 12; j++) W12[(size_t)j * Kp + k] = 0.f;
        }
    }
    if (blk == 0) {
        if (tid < 10) {
            float a = b2[tid];
            for (int r = 0; r < 500; r++) a += l2[tid * 500 + r] * b1[r];
            bc12[tid] = a;
        } else if (tid < 12) {
            bc12[tid] = db[tid - 10];
        }
    }
}

__global__ __launch_bounds__(256) void prep_kernel(
    const float* l1c1_w, const float* l1c1_b, const float* l2c1_w, const float* l2c1_b,
    const float* l1c2_w, const float* l1c2_b, const float* l2c2_w, const float* l2c2_b,
    const float* d1_w, const float* d1_b, const float* d2_w, const float* d2_b,
    const float* c2_w,
    float* W1, float* b1c, float* W2, float* b2c, float2* wpk2)
{
    __shared__ __align__(16) float l2T[500 * 12];
    int bx = blockIdx.x, tid = threadIdx.x;
    if (bx < 34) {
        combine_part(l1c1_w, l1c1_b, l2c1_w, l2c1_b, d1_w, d1_b, K1, KP1P, W1, b1c, bx, l2T);
    } else if (bx < 40) {
        combine_part(l1c2_w, l1c2_b, l2c2_w, l2c2_b, d2_w, d2_b, K2, KP2P, W2, b2c, bx - 34, l2T);
    } else {
        int i = (bx - 40) * 256 + tid;
        if (i < 22500) {
            int oc = i / 450, r = i - oc * 450;
            int ic = r / 9, k = r - ic * 9;
            float v = c2_w[i];
            wpk2[ic * 500 + oc * 10 + k] = make_float2(v, v);   // pad k=9 stays zero
        }
    }
}

// ---------------- conv1: register patch + packed f32x2 ----------------------
__global__ __launch_bounds__(192) void conv1_kernel(
    const float* __restrict__ x, const float* __restrict__ w,
    const float* __restrict__ bias, float* __restrict__ h1)
{
    int b = blockIdx.x;
    __shared__ __align__(16) float xs[784];
    __shared__ __align__(16) float2 ws[450];
    __shared__ __align__(16) float bs[50];
    int tid = threadIdx.x;
    {
        const float4* xb = (const float4*)(x + (size_t)b * 784);
        for (int i = tid; i < 196; i += 192) ((float4*)xs)[i] = xb[i];
        for (int i = tid; i < 450; i += 192) { float v = w[i]; ws[i] = make_float2(v, v); }
        for (int i = tid; i < 50;  i += 192) bs[i] = bias[i];
    }
    __syncthreads();
    if (tid >= 169) return;

    const int py = tid / 13, px = tid % 13;
    const int Y = 2 * py, X = 2 * px;
    float p[4][4];
    #pragma unroll
    for (int r = 0; r < 4; r++)
        #pragma unroll
        for (int c = 0; c < 4; c++) p[r][c] = xs[(Y + r) * 28 + X + c];
    unsigned long long P[4][3];
    #pragma unroll
    for (int r = 0; r < 4; r++)
        #pragma unroll
        for (int k = 0; k < 3; k++)
            asm("mov.b64 %0, {%1, %2};" : "=l"(P[r][k])
                : "r"(__float_as_uint(p[r][k])), "r"(__float_as_uint(p[r][k + 1])));

    float* hb = h1 + (size_t)b * KP1P + tid;
    for (int oc = 0; oc < 50; oc++) {
        unsigned long long aT = 0ULL, aB = 0ULL;
        #pragma unroll
        for (int ky = 0; ky < 3; ky++)
            #pragma unroll
            for (int kx = 0; kx < 3; kx++) {
                unsigned long long w2 = *(const unsigned long long*)&ws[oc * 9 + ky * 3 + kx];
                asm("fma.rn.f32x2 %0, %1, %2, %0;" : "+l"(aT) : "l"(P[ky][kx]), "l"(w2));
                asm("fma.rn.f32x2 %0, %1, %2, %0;" : "+l"(aB) : "l"(P[ky + 1][kx]), "l"(w2));
            }
        unsigned int u0, u1, u2, u3;
        asm("mov.b64 {%0, %1}, %2;" : "=r"(u0), "=r"(u1) : "l"(aT));
        asm("mov.b64 {%0, %1}, %2;" : "=r"(u2), "=r"(u3) : "l"(aB));
        float m = fmaxf(fmaxf(__uint_as_float(u0), __uint_as_float(u1)),
                        fmaxf(__uint_as_float(u2), __uint_as_float(u3)));
        m += bs[oc];
        hb[oc * 169] = fmaxf(m, 0.f);
    }
}

// ====== stagehead (stage 1): direct-LDG streamer, no smem, no barriers ======
__global__ __launch_bounds__(256) void stagehead_part_kernel(
    const float* __restrict__ f, int Kp,
    const float* __restrict__ W12, float* __restrict__ part)
{
    const int tid = threadIdx.x, lane = tid & 31, wid = tid >> 5;
    const int b0 = blockIdx.x * 16;
    const int split = blockIdx.y;
    const int s0 = b0 + wid * 2, s1 = s0 + 1;
    const int half = Kp >> 1;
    const int kBeg = split * half;
    const int kEnd = kBeg + half;

    float acc0[12], acc1[12];
    #pragma unroll
    for (int j = 0; j < 12; j++) { acc0[j] = 0.f; acc1[j] = 0.f; }

    const float* f0p = f + (size_t)s0 * Kp;
    const float* f1p = f + (size_t)s1 * Kp;

    #pragma unroll 2
    for (int k = kBeg + lane * 4; k < kEnd; k += 128) {
        float4 a0 = *(const float4*)(f0p + k);
        float4 a1 = *(const float4*)(f1p + k);
        #pragma unroll
        for (int j = 0; j < 12; j++) {
            float4 w = __ldg((const float4*)&W12[(size_t)j * Kp + k]);
            acc0[j] = fmaf(a0.x, w.x, fmaf(a0.y, w.y, fmaf(a0.z, w.z, fmaf(a0.w, w.w, acc0[j]))));
            acc1[j] = fmaf(a1.x, w.x, fmaf(a1.y, w.y, fmaf(a1.z, w.z, fmaf(a1.w, w.w, acc1[j]))));
        }
    }

    #pragma unroll
    for (int j = 0; j < 12; j++) {
        #pragma unroll
        for (int off = 16; off; off >>= 1) {
            acc0[j] += __shfl_xor_sync(0xffffffffu, acc0[j], off);
            acc1[j] += __shfl_xor_sync(0xffffffffu, acc1[j], off);
        }
    }
    if (lane == 0) {
        #pragma unroll
        for (int j = 0; j < 12; j++) {
            part[s0 * 24 + split * 12 + j] = acc0[j];
            part[s1 * 24 + split * 12 + j] = acc1[j];
        }
    }
}

// ====== conv2 mega: conv2 + stage-2 head + conv3 (h2 never leaves smem) =====
// dyn smem bytes:
//   hs   @0      : 50*182*4 = 36400 (pad 36416)
//   wb   @36416  : 2500 float2 = 20000  (single-buffered 5-ic tile)
//   h2s  @56416  : 1250*4 = 5000
//   bss  @61416  : 200
//   red  @61616  : 108*4 = 432 (pad 448)
//   red3 @62064  : 1000*4 = 4000
#define C2_SMEM 66064
__global__ __launch_bounds__(256, 3) void conv2_kernel(
    const float* __restrict__ h1, const float2* __restrict__ wpk,
    const float* __restrict__ bias, const float* __restrict__ part,
    const float* __restrict__ b1c,
    const float* __restrict__ W2, const float* __restrict__ b2c,
    const float* __restrict__ c3_w, const float* __restrict__ c3_b,
    int* __restrict__ e1, int* __restrict__ e2,
    float* __restrict__ o2, float* __restrict__ f3)
{
    extern __shared__ __align__(16) char csm[];
    float*  hs   = (float*)csm;
    float2* wb   = (float2*)(csm + 36416);
    float*  h2s  = (float*)(csm + 56416);
    float*  bss  = (float*)(csm + 61416);
    float*  red  = (float*)(csm + 61616);
    float*  red3 = (float*)(csm + 62064);
    __shared__ int sflag;

    const int b = blockIdx.x;
    const int tid = threadIdx.x;
    if (tid == 0) {
        float m0 = part[b * 24 + 10] + part[b * 24 + 22] + __ldg(&b1c[10]);
        float m1 = part[b * 24 + 11] + part[b * 24 + 23] + __ldg(&b1c[11]);
        int fl = (m0 >= m1) ? 1 : 0;
        e1[b] = fl;
        sflag = fl;
        if (fl) e2[b] = 0;     // deterministic; unused when e1 selected
    }
    __syncthreads();
    if (sflag) return;

    {
        const float* hb = h1 + (size_t)b * KP1P;
        for (int i = tid; i < 8450; i += 256) {
            int ic = i / 169, rem = i - ic * 169;
            int r = rem / 13, c = rem - r * 13;
            hs[ic * 182 + r * 14 + c] = hb[i];
        }
        for (int i = tid; i < 50; i += 256) bss[i] = bias[i];
    }

    const int osub = tid / 25, pos = tid % 25;
    const int oc0 = osub * 5;
    const int py = pos / 5, px = pos % 5;
    const int Y = 2 * py, X = 2 * px;
    const bool active = (tid < 250);

    unsigned long long aT[5], aB[5];
    #pragma unroll
    for (int j = 0; j < 5; j++) { aT[j] = 0ULL; aB[j] = 0ULL; }

    for (int t = 0; t < 10; t++) {
        __syncthreads();   // previous tile consumed (and hs staged on t=0)
        {
            const float4* src = (const float4*)wpk + t * 1250;
            for (int i = tid; i < 1250; i += 256) ((float4*)wb)[i] = src[i];
        }
        __syncthreads();
        if (active) {
            #pragma unroll
            for (int i5 = 0; i5 < 5; i5++) {
                const float* hc = hs + (t * 5 + i5) * 182;
                unsigned long long P[4][3];
                #pragma unroll
                for (int r = 0; r < 4; r++) {
                    float2 v0 = *(const float2*)(hc + (Y + r) * 14 + X);
                    float2 v1 = *(const float2*)(hc + (Y + r) * 14 + X + 2);
                    asm("mov.b64 %0, {%1, %2};" : "=l"(P[r][0])
                        : "r"(__float_as_uint(v0.x)), "r"(__float_as_uint(v0.y)));
                    asm("mov.b64 %0, {%1, %2};" : "=l"(P[r][1])
                        : "r"(__float_as_uint(v0.y)), "r"(__float_as_uint(v1.x)));
                    asm("mov.b64 %0, {%1, %2};" : "=l"(P[r][2])
                        : "r"(__float_as_uint(v1.x)), "r"(__float_as_uint(v1.y)));
                }
                const float2* wrow = wb + (i5 * 50 + oc0) * 10;
                #pragma unroll
                for (int j = 0; j < 5; j++) {
                    const float2* wp = wrow + j * 10;
                    ulonglong2 q0 = *(const ulonglong2*)(wp);
                    ulonglong2 q1 = *(const ulonglong2*)(wp + 2);
                    ulonglong2 q2 = *(const ulonglong2*)(wp + 4);
                    ulonglong2 q3 = *(const ulonglong2*)(wp + 6);
                    unsigned long long w8 = *(const unsigned long long*)(wp + 8);
                    unsigned long long wv[9] = {q0.x, q0.y, q1.x, q1.y,
                                                q2.x, q2.y, q3.x, q3.y, w8};
                    #pragma unroll
                    for (int ky = 0; ky < 3; ky++)
                        #pragma unroll
                        for (int kx = 0; kx < 3; kx++) {
                            asm("fma.rn.f32x2 %0, %1, %2, %0;"
                                : "+l"(aT[j]) : "l"(P[ky][kx]), "l"(wv[ky * 3 + kx]));
                            asm("fma.rn.f32x2 %0, %1, %2, %0;"
                                : "+l"(aB[j]) : "l"(P[ky + 1][kx]), "l"(wv[ky * 3 + kx]));
                        }
                }
            }
        }
    }

    // finalize conv outputs into smem h2s + per-thread head partials
    float hd[12];
    #pragma unroll
    for (int jj = 0; jj < 12; jj++) hd[jj] = 0.f;
    if (active) {
        float v5[5];
        #pragma unroll
        for (int j = 0; j < 5; j++) {
            unsigned int u0, u1, u2, u3;
            asm("mov.b64 {%0, %1}, %2;" : "=r"(u0), "=r"(u1) : "l"(aT[j]));
            asm("mov.b64 {%0, %1}, %2;" : "=r"(u2), "=r"(u3) : "l"(aB[j]));
            float m = fmaxf(fmaxf(__uint_as_float(u0), __uint_as_float(u1)),
                            fmaxf(__uint_as_float(u2), __uint_as_float(u3)));
            m += bss[oc0 + j];
            v5[j] = fmaxf(m, 0.f);
            h2s[(oc0 + j) * 25 + pos] = v5[j];
        }
        #pragma unroll
        for (int jj = 0; jj < 12; jj++) {
            float s = 0.f;
            #pragma unroll
            for (int j = 0; j < 5; j++)
                s += v5[j] * __ldg(&W2[(size_t)jj * KP2P + (oc0 + j) * 25 + pos]);
            hd[jj] = s;
        }
    }
    // block reduce 12 sums
    const int lane = tid & 31, wrp = tid >> 5;
    #pragma unroll
    for (int jj = 0; jj < 12; jj++) {
        #pragma unroll
        for (int off = 16; off; off >>= 1)
            hd[jj] += __shfl_xor_sync(0xffffffffu, hd[jj], off);
    }
    if (lane == 0) {
        #pragma unroll
        for (int jj = 0; jj < 12; jj++) red[jj * 8 + wrp] = hd[jj];
    }
    __syncthreads();
    if (tid < 12) {
        float s = __ldg(&b2c[tid]);
        #pragma unroll
        for (int w = 0; w < 8; w++) s += red[tid * 8 + w];
        red[96 + tid] = s;
    }
    __syncthreads();

    const float em0 = red[96 + 10], em1 = red[96 + 11];
    if (tid == 0) e2[b] = (em0 >= em1) ? 1 : 0;
    if (tid < 10) o2[b * 10 + tid] = red[96 + tid];
    if (em0 >= em1) return;    // uniform: exit at stage 2, no conv3 needed

    // ---- fused conv3: h2s (smem) -> f3 ----
    if (tid < 250) {
        const int oc2 = tid % 50, grp = tid / 50;
        const float* w3 = c3_w + oc2 * 450 + grp * 90;
        float a0 = 0.f, a1 = 0.f, a2 = 0.f, a3 = 0.f;
        #pragma unroll
        for (int i2 = 0; i2 < 10; i2++) {
            const float* hc = h2s + (grp * 10 + i2) * 25;
            #pragma unroll
            for (int ky = 0; ky < 3; ky++)
                #pragma unroll
                for (int kx = 0; kx < 3; kx++) {
                    float wv = __ldg(&w3[i2 * 9 + ky * 3 + kx]);
                    a0 += hc[ky * 5 + kx] * wv;
                    a1 += hc[ky * 5 + kx + 1] * wv;
                    a2 += hc[(ky + 1) * 5 + kx] * wv;
                    a3 += hc[(ky + 1) * 5 + kx + 1] * wv;
                }
        }
        float* r3 = red3 + grp * 200 + oc2 * 4;
        r3[0] = a0; r3[1] = a1; r3[2] = a2; r3[3] = a3;
    }
    __syncthreads();
    if (tid < 50) {
        float a0 = 0.f, a1 = 0.f, a2 = 0.f, a3 = 0.f;
        #pragma unroll
        for (int g = 0; g < 5; g++) {
            const float* r3 = red3 + g * 200 + tid * 4;
            a0 += r3[0]; a1 += r3[1]; a2 += r3[2]; a3 += r3[3];
        }
        float m = fmaxf(fmaxf(a0, a1), fmaxf(a2, a3)) + __ldg(&c3_b[tid]);
        f3[b * 50 + tid] = fmaxf(m, 0.f);
    }
}

// ==== stage3 + final fused ===================================================
#define S3_G 32
#define S3_SMEM ((25000 + 5000 + 500 + S3_G * 50 + S3_G * 500 + S3_G * 10) * 4)

__global__ __launch_bounds__(256) void stage3final_kernel(
    const float* __restrict__ f3,
    const float* __restrict__ l1w, const float* __restrict__ l1b,
    const float* __restrict__ l2w, const float* __restrict__ l2b,
    const int* __restrict__ e1, const int* __restrict__ e2,
    const float* __restrict__ part, const float* __restrict__ b1c,
    const float* __restrict__ o2, float* __restrict__ out)
{
    extern __shared__ __align__(16) float sm[];
    float* w1  = sm;
    float* w2  = sm + 25000;
    float* b1  = sm + 30000;
    float* fs  = sm + 30500;
    float* hid = sm + 32100;
    float* o3s = sm + 48100;
    int tid = threadIdx.x;
    int b0 = blockIdx.x * S3_G;

    for (int i = tid; i < 25000; i += 256) w1[i] = l1w[i];
    for (int i = tid; i < 5000;  i += 256) w2[i] = l2w[i];
    for (int i = tid; i < 500;   i += 256) b1[i] = l1b[i];
    for (int i = tid; i < S3_G * 50; i += 256) fs[i] = f3[b0 * 50 + i];
    __syncthreads();

    for (int hh = tid; hh < S3_G * 500; hh += 256) {
        int s = hh / 500, j = hh - s * 500;
        float a = b1[j];
        const float* fr = fs + s * 50;
        const float* wr = w1 + j * 50;
        #pragma unroll 10
        for (int k = 0; k < 50; k++) a += fr[k] * wr[k];
        hid[hh] = fmaxf(a, 0.f);
    }
    __syncthreads();

    for (int oo = tid; oo < S3_G * 10; oo += 256) {
        int s = oo / 10, n = oo - s * 10;
        float a = __ldg(&l2b[n]);
        const float* hr = hid + s * 500;
        const float* wr = w2 + n * 500;
        #pragma unroll 4
        for (int j = 0; j < 500; j++) a += hr[j] * wr[j];
        o3s[s * 10 + n] = a;
    }
    __syncthreads();

    if (tid < S3_G) {
        int b = b0 + tid;
        float v[10];
        if (e1[b]) {
            #pragma unroll
            for (int j = 0; j < 10; j++)
                v[j] = part[b * 24 + j] + part[b * 24 + 12 + j] + __ldg(&b1c[j]);
        } else if (e2[b]) {
            #pragma unroll
            for (int j = 0; j < 10; j++) v[j] = o2[b * 10 + j];
        } else {
            #pragma unroll
            for (int j = 0; j < 10; j++) v[j] = o3s[tid * 10 + j];
        }
        float mx = -1e30f;
        #pragma unroll
        for (int j = 0; j < 10; j++) mx = fmaxf(mx, v[j]);
        float sum = 0.f;
        #pragma unroll
        for (int j = 0; j < 10; j++) sum += expf(v[j] - mx);
        float l = logf(sum);
        #pragma unroll
        for (int j = 0; j < 10; j++) out[b * 10 + j] = v[j] - mx - l;
    }
}

// ---------------- launch ----------------------------------------------------
extern "C" void kernel_launch(void* const* d_in, const int* in_sizes, int n_in,
                              void* d_out, int out_size)
{
    const float* x      = (const float*)d_in[0];
    const float* c1_w   = (const float*)d_in[1];
    const float* c1_b   = (const float*)d_in[2];
    const float* c2_w   = (const float*)d_in[3];
    const float* c2_b   = (const float*)d_in[4];
    const float* c3_w   = (const float*)d_in[5];
    const float* c3_b   = (const float*)d_in[6];
    const float* l1c1_w = (const float*)d_in[7];
    const float* l1c1_b = (const float*)d_in[8];
    const float* l2c1_w = (const float*)d_in[9];
    const float* l2c1_b = (const float*)d_in[10];
    const float* l1c2_w = (const float*)d_in[11];
    const float* l1c2_b = (const float*)d_in[12];
    const float* l2c2_w = (const float*)d_in[13];
    const float* l2c2_b = (const float*)d_in[14];
    const float* l1_w   = (const float*)d_in[15];
    const float* l1_b   = (const float*)d_in[16];
    const float* l2_w   = (const float*)d_in[17];
    const float* l2_b   = (const float*)d_in[18];
    const float* d1_w   = (const float*)d_in[19];
    const float* d1_b   = (const float*)d_in[20];
    const float* d2_w   = (const float*)d_in[21];
    const float* d2_b   = (const float*)d_in[22];
    float* out = (float*)d_out;

    float *h1, *f3, *o2, *W1, *W2, *b1c, *b2c, *part1;
    float2 *wpk2;
    int *e1, *e2;
    cudaGetSymbolAddress((void**)&h1,   g_h1);
    cudaGetSymbolAddress((void**)&f3,   g_f3);
    cudaGetSymbolAddress((void**)&o2,   g_o2);
    cudaGetSymbolAddress((void**)&e1,   g_e1);
    cudaGetSymbolAddress((void**)&e2,   g_e2);
    cudaGetSymbolAddress((void**)&W1,   g_W1);
    cudaGetSymbolAddress((void**)&W2,   g_W2);
    cudaGetSymbolAddress((void**)&b1c,  g_b1c);
    cudaGetSymbolAddress((void**)&b2c,  g_b2c);
    cudaGetSymbolAddress((void**)&part1, g_part1);
    cudaGetSymbolAddress((void**)&wpk2, g_wpk2);

    static cudaStream_t s2 = nullptr;
    static cudaEvent_t evA = nullptr, evB = nullptr;
    static int attr_set = 0;
    if (!attr_set) {
        cudaFuncSetAttribute(conv2_kernel,
                             cudaFuncAttributeMaxDynamicSharedMemorySize, C2_SMEM);
        cudaFuncSetAttribute(stage3final_kernel,
                             cudaFuncAttributeMaxDynamicSharedMemorySize, S3_SMEM);
        cudaStreamCreateWithFlags(&s2, cudaStreamNonBlocking);
        cudaEventCreateWithFlags(&evA, cudaEventDisableTiming);
        cudaEventCreateWithFlags(&evB, cudaEventDisableTiming);
        attr_set = 1;
    }

    // fork: prep on side stream, conv1 on main stream (independent)
    cudaEventRecord(evA, 0);
    cudaStreamWaitEvent(s2, evA, 0);
    prep_kernel<<<128, 256, 0, s2>>>(l1c1_w, l1c1_b, l2c1_w, l2c1_b,
                                     l1c2_w, l1c2_b, l2c2_w, l2c2_b,
                                     d1_w, d1_b, d2_w, d2_b, c2_w,
                                     W1, b1c, W2, b2c, wpk2);
    cudaEventRecord(evB, s2);

    conv1_kernel<<<BATCH, 192>>>(x, c1_w, c1_b, h1);

    // join: sh1 needs W1 (prep) + h1 (conv1)
    cudaStreamWaitEvent(0, evB, 0);
    stagehead_part_kernel<<<dim3(BATCH / 16, 2), 256>>>(h1, KP1P, W1, part1);

    // stage 2+3 mega: conv2 + head (e1/e2/o2) + conv3 (f3), h2 stays in smem
    conv2_kernel<<<BATCH, 256, C2_SMEM>>>(h1, wpk2, c2_b, part1, b1c,
                                          W2, b2c, c3_w, c3_b, e1, e2, o2, f3);

    // stage 3 MLP + final select/log_softmax
    stage3final_kernel<<<BATCH / S3_G, 256, S3_SMEM>>>(
        f3, l1_w, l1_b, l2_w, l2_b, e1, e2, part1, b1c, o2, out);
}

// round 13
// speedup vs baseline: 1.0075x; 1.0075x over previous
#include <cuda_runtime.h>
#include <math.h>
#include <stdint.h>

#define BATCH 4096
#define K1 8450
#define K2 1250
#define KP1P 8704          // h1 row pitch (17 * 512)
#define KP2P 1536          // W2 row pitch

// ---------------- scratch (device globals; zero-initialized) ---------------
__device__ float g_h1[(size_t)BATCH * KP1P];
__device__ float g_f3[BATCH * 50];
__device__ float g_o2[BATCH * 10];
__device__ int   g_e1[BATCH];
__device__ int   g_e2[BATCH];
__device__ float g_W1[12 * KP1P];    // rows 0-9: l2c1@l1c1; 10-11: d1_w
__device__ float g_W2[12 * KP2P];
__device__ float g_b1c[12];
__device__ float g_b2c[12];
__device__ float g_part1[BATCH * 24];  // [b][split(2)][12]
__device__ float2 g_wpk2[50 * 500];    // conv2 weights [ic][oc][10] dup, pad k=9 zero

// ================= merged prep kernel =======================================
__device__ void combine_part(
    const float* __restrict__ l1, const float* __restrict__ b1,
    const float* __restrict__ l2, const float* __restrict__ b2,
    const float* __restrict__ dw, const float* __restrict__ db,
    int K, int Kp, float* __restrict__ W12, float* __restrict__ bc12,
    int blk, float* l2T)
{
    int tid = threadIdx.x;
    for (int i = tid; i < 5000; i += 256) {
        int j = i / 500, r = i - j * 500;
        l2T[r * 12 + j] = l2[i];
    }
    for (int r = tid; r < 500; r += 256) { l2T[r * 12 + 10] = 0.f; l2T[r * 12 + 11] = 0.f; }
    __syncthreads();

    int k = blk * 256 + tid;
    if (k < Kp) {
        if (k < K) {
            float acc[10];
            #pragma unroll
            for (int j = 0; j < 10; j++) acc[j] = 0.f;
            #pragma unroll 4
            for (int r = 0; r < 500; r++) {
                float a = __ldg(&l1[(size_t)r * K + k]);
                float4 w0 = *(const float4*)&l2T[r * 12];
                float4 w1 = *(const float4*)&l2T[r * 12 + 4];
                float2 w2 = *(const float2*)&l2T[r * 12 + 8];
                acc[0] += a * w0.x; acc[1] += a * w0.y; acc[2] += a * w0.z; acc[3] += a * w0.w;
                acc[4] += a * w1.x; acc[5] += a * w1.y; acc[6] += a * w1.z; acc[7] += a * w1.w;
                acc[8] += a * w2.x; acc[9] += a * w2.y;
            }
            #pragma unroll
            for (int j = 0; j < 10; j++) W12[(size_t)j * Kp + k] = acc[j];
            W12[(size_t)10 * Kp + k] = __ldg(&dw[k]);
            W12[(size_t)11 * Kp + k] = __ldg(&dw[K + k]);
        } else {
            #pragma unroll
            for (int j = 0; j < 12; j++) W12[(size_t)j * Kp + k] = 0.f;
        }
    }
    if (blk == 0) {
        if (tid < 10) {
            float a = b2[tid];
            for (int r = 0; r < 500; r++) a += l2[tid * 500 + r] * b1[r];
            bc12[tid] = a;
        } else if (tid < 12) {
            bc12[tid] = db[tid - 10];
        }
    }
}

__global__ __launch_bounds__(256) void prep_kernel(
    const float* l1c1_w, const float* l1c1_b, const float* l2c1_w, const float* l2c1_b,
    const float* l1c2_w, const float* l1c2_b, const float* l2c2_w, const float* l2c2_b,
    const float* d1_w, const float* d1_b, const float* d2_w, const float* d2_b,
    const float* c2_w,
    float* W1, float* b1c, float* W2, float* b2c, float2* wpk2)
{
    __shared__ __align__(16) float l2T[500 * 12];
    int bx = blockIdx.x, tid = threadIdx.x;
    if (bx < 34) {
        combine_part(l1c1_w, l1c1_b, l2c1_w, l2c1_b, d1_w, d1_b, K1, KP1P, W1, b1c, bx, l2T);
    } else if (bx < 40) {
        combine_part(l1c2_w, l1c2_b, l2c2_w, l2c2_b, d2_w, d2_b, K2, KP2P, W2, b2c, bx - 34, l2T);
    } else {
        int i = (bx - 40) * 256 + tid;
        if (i < 22500) {
            int oc = i / 450, r = i - oc * 450;
            int ic = r / 9, k = r - ic * 9;
            float v = c2_w[i];
            wpk2[ic * 500 + oc * 10 + k] = make_float2(v, v);   // pad k=9 stays zero
        }
    }
}

// ---------------- conv1: register patch + packed f32x2 ----------------------
__global__ __launch_bounds__(192) void conv1_kernel(
    const float* __restrict__ x, const float* __restrict__ w,
    const float* __restrict__ bias, float* __restrict__ h1)
{
    int b = blockIdx.x;
    __shared__ __align__(16) float xs[784];
    __shared__ __align__(16) float2 ws[450];
    __shared__ __align__(16) float bs[50];
    int tid = threadIdx.x;
    {
        const float4* xb = (const float4*)(x + (size_t)b * 784);
        for (int i = tid; i < 196; i += 192) ((float4*)xs)[i] = xb[i];
        for (int i = tid; i < 450; i += 192) { float v = w[i]; ws[i] = make_float2(v, v); }
        for (int i = tid; i < 50;  i += 192) bs[i] = bias[i];
    }
    __syncthreads();
    if (tid >= 169) return;

    const int py = tid / 13, px = tid % 13;
    const int Y = 2 * py, X = 2 * px;
    float p[4][4];
    #pragma unroll
    for (int r = 0; r < 4; r++)
        #pragma unroll
        for (int c = 0; c < 4; c++) p[r][c] = xs[(Y + r) * 28 + X + c];
    unsigned long long P[4][3];
    #pragma unroll
    for (int r = 0; r < 4; r++)
        #pragma unroll
        for (int k = 0; k < 3; k++)
            asm("mov.b64 %0, {%1, %2};" : "=l"(P[r][k])
                : "r"(__float_as_uint(p[r][k])), "r"(__float_as_uint(p[r][k + 1])));

    float* hb = h1 + (size_t)b * KP1P + tid;
    for (int oc = 0; oc < 50; oc++) {
        unsigned long long aT = 0ULL, aB = 0ULL;
        #pragma unroll
        for (int ky = 0; ky < 3; ky++)
            #pragma unroll
            for (int kx = 0; kx < 3; kx++) {
                unsigned long long w2 = *(const unsigned long long*)&ws[oc * 9 + ky * 3 + kx];
                asm("fma.rn.f32x2 %0, %1, %2, %0;" : "+l"(aT) : "l"(P[ky][kx]), "l"(w2));
                asm("fma.rn.f32x2 %0, %1, %2, %0;" : "+l"(aB) : "l"(P[ky + 1][kx]), "l"(w2));
            }
        unsigned int u0, u1, u2, u3;
        asm("mov.b64 {%0, %1}, %2;" : "=r"(u0), "=r"(u1) : "l"(aT));
        asm("mov.b64 {%0, %1}, %2;" : "=r"(u2), "=r"(u3) : "l"(aB));
        float m = fmaxf(fmaxf(__uint_as_float(u0), __uint_as_float(u1)),
                        fmaxf(__uint_as_float(u2), __uint_as_float(u3)));
        m += bs[oc];
        hb[oc * 169] = fmaxf(m, 0.f);
    }
}

// ====== stagehead (stage 1): direct-LDG streamer, no smem, no barriers ======
__global__ __launch_bounds__(256) void stagehead_part_kernel(
    const float* __restrict__ f, int Kp,
    const float* __restrict__ W12, float* __restrict__ part)
{
    const int tid = threadIdx.x, lane = tid & 31, wid = tid >> 5;
    const int b0 = blockIdx.x * 16;
    const int split = blockIdx.y;
    const int s0 = b0 + wid * 2, s1 = s0 + 1;
    const int half = Kp >> 1;
    const int kBeg = split * half;
    const int kEnd = kBeg + half;

    float acc0[12], acc1[12];
    #pragma unroll
    for (int j = 0; j < 12; j++) { acc0[j] = 0.f; acc1[j] = 0.f; }

    const float* f0p = f + (size_t)s0 * Kp;
    const float* f1p = f + (size_t)s1 * Kp;

    #pragma unroll 2
    for (int k = kBeg + lane * 4; k < kEnd; k += 128) {
        float4 a0 = *(const float4*)(f0p + k);
        float4 a1 = *(const float4*)(f1p + k);
        #pragma unroll
        for (int j = 0; j < 12; j++) {
            float4 w = __ldg((const float4*)&W12[(size_t)j * Kp + k]);
            acc0[j] = fmaf(a0.x, w.x, fmaf(a0.y, w.y, fmaf(a0.z, w.z, fmaf(a0.w, w.w, acc0[j]))));
            acc1[j] = fmaf(a1.x, w.x, fmaf(a1.y, w.y, fmaf(a1.z, w.z, fmaf(a1.w, w.w, acc1[j]))));
        }
    }

    #pragma unroll
    for (int j = 0; j < 12; j++) {
        #pragma unroll
        for (int off = 16; off; off >>= 1) {
            acc0[j] += __shfl_xor_sync(0xffffffffu, acc0[j], off);
            acc1[j] += __shfl_xor_sync(0xffffffffu, acc1[j], off);
        }
    }
    if (lane == 0) {
        #pragma unroll
        for (int j = 0; j < 12; j++) {
            part[s0 * 24 + split * 12 + j] = acc0[j];
            part[s1 * 24 + split * 12 + j] = acc1[j];
        }
    }
}

// ====== conv2 mega: conv2 + stage-2 head + conv3, double-buffered weights ===
// dyn smem bytes:
//   hs   @0      : 36416
//   wb   @36416  : 2*2500 float2 = 40000
//   h2s  @76416  : 5000
//   bss  @81416  : 200
//   red  @81616  : 448
//   red3 @82064  : 4000
#define C2_SMEM 86064
__global__ __launch_bounds__(256, 2) void conv2_kernel(
    const float* __restrict__ h1, const float2* __restrict__ wpk,
    const float* __restrict__ bias, const float* __restrict__ part,
    const float* __restrict__ b1c,
    const float* __restrict__ W2, const float* __restrict__ b2c,
    const float* __restrict__ c3_w, const float* __restrict__ c3_b,
    int* __restrict__ e1, int* __restrict__ e2,
    float* __restrict__ o2, float* __restrict__ f3)
{
    extern __shared__ __align__(16) char csm[];
    float*  hs   = (float*)csm;
    float2* wb   = (float2*)(csm + 36416);
    float*  h2s  = (float*)(csm + 76416);
    float*  bss  = (float*)(csm + 81416);
    float*  red  = (float*)(csm + 81616);
    float*  red3 = (float*)(csm + 82064);
    __shared__ int sflag;

    const int b = blockIdx.x;
    const int tid = threadIdx.x;
    if (tid == 0) {
        float m0 = part[b * 24 + 10] + part[b * 24 + 22] + __ldg(&b1c[10]);
        float m1 = part[b * 24 + 11] + part[b * 24 + 23] + __ldg(&b1c[11]);
        int fl = (m0 >= m1) ? 1 : 0;
        e1[b] = fl;
        sflag = fl;
        if (fl) e2[b] = 0;     // deterministic; unused when e1 selected
    }
    __syncthreads();
    if (sflag) return;

    {
        const float* hb = h1 + (size_t)b * KP1P;
        for (int i = tid; i < 8450; i += 256) {
            int ic = i / 169, rem = i - ic * 169;
            int r = rem / 13, c = rem - r * 13;
            hs[ic * 182 + r * 14 + c] = hb[i];
        }
        for (int i = tid; i < 50; i += 256) bss[i] = bias[i];
        // weight tile 0
        for (int i = tid; i < 1250; i += 256)
            ((float4*)wb)[i] = ((const float4*)wpk)[i];
    }
    __syncthreads();

    const int osub = tid / 25, pos = tid % 25;
    const int oc0 = osub * 5;
    const int py = pos / 5, px = pos % 5;
    const int Y = 2 * py, X = 2 * px;
    const bool active = (tid < 250);

    unsigned long long aT[5], aB[5];
    #pragma unroll
    for (int j = 0; j < 5; j++) { aT[j] = 0ULL; aB[j] = 0ULL; }

    for (int t = 0; t < 10; t++) {
        const int cur = t & 1;
        if (t + 1 < 10) {
            const float4* src = (const float4*)wpk + (t + 1) * 1250;
            float4* dst = (float4*)(wb + (cur ^ 1) * 2500);
            for (int i = tid; i < 1250; i += 256) dst[i] = src[i];
        }
        if (active) {
            #pragma unroll
            for (int i5 = 0; i5 < 5; i5++) {
                const float* hc = hs + (t * 5 + i5) * 182;
                unsigned long long P[4][3];
                #pragma unroll
                for (int r = 0; r < 4; r++) {
                    float2 v0 = *(const float2*)(hc + (Y + r) * 14 + X);
                    float2 v1 = *(const float2*)(hc + (Y + r) * 14 + X + 2);
                    asm("mov.b64 %0, {%1, %2};" : "=l"(P[r][0])
                        : "r"(__float_as_uint(v0.x)), "r"(__float_as_uint(v0.y)));
                    asm("mov.b64 %0, {%1, %2};" : "=l"(P[r][1])
                        : "r"(__float_as_uint(v0.y)), "r"(__float_as_uint(v1.x)));
                    asm("mov.b64 %0, {%1, %2};" : "=l"(P[r][2])
                        : "r"(__float_as_uint(v1.x)), "r"(__float_as_uint(v1.y)));
                }
                const float2* wrow = wb + cur * 2500 + (i5 * 50 + oc0) * 10;
                #pragma unroll
                for (int j = 0; j < 5; j++) {
                    const float2* wp = wrow + j * 10;
                    ulonglong2 q0 = *(const ulonglong2*)(wp);
                    ulonglong2 q1 = *(const ulonglong2*)(wp + 2);
                    ulonglong2 q2 = *(const ulonglong2*)(wp + 4);
                    ulonglong2 q3 = *(const ulonglong2*)(wp + 6);
                    unsigned long long w8 = *(const unsigned long long*)(wp + 8);
                    unsigned long long wv[9] = {q0.x, q0.y, q1.x, q1.y,
                                                q2.x, q2.y, q3.x, q3.y, w8};
                    #pragma unroll
                    for (int ky = 0; ky < 3; ky++)
                        #pragma unroll
                        for (int kx = 0; kx < 3; kx++) {
                            asm("fma.rn.f32x2 %0, %1, %2, %0;"
                                : "+l"(aT[j]) : "l"(P[ky][kx]), "l"(wv[ky * 3 + kx]));
                            asm("fma.rn.f32x2 %0, %1, %2, %0;"
                                : "+l"(aB[j]) : "l"(P[ky + 1][kx]), "l"(wv[ky * 3 + kx]));
                        }
                }
            }
        }
        __syncthreads();
    }

    // finalize conv outputs into smem h2s + per-thread head partials
    float hd[12];
    #pragma unroll
    for (int jj = 0; jj < 12; jj++) hd[jj] = 0.f;
    if (active) {
        float v5[5];
        #pragma unroll
        for (int j = 0; j < 5; j++) {
            unsigned int u0, u1, u2, u3;
            asm("mov.b64 {%0, %1}, %2;" : "=r"(u0), "=r"(u1) : "l"(aT[j]));
            asm("mov.b64 {%0, %1}, %2;" : "=r"(u2), "=r"(u3) : "l"(aB[j]));
            float m = fmaxf(fmaxf(__uint_as_float(u0), __uint_as_float(u1)),
                            fmaxf(__uint_as_float(u2), __uint_as_float(u3)));
            m += bss[oc0 + j];
            v5[j] = fmaxf(m, 0.f);
            h2s[(oc0 + j) * 25 + pos] = v5[j];
        }
        #pragma unroll
        for (int jj = 0; jj < 12; jj++) {
            float s = 0.f;
            #pragma unroll
            for (int j = 0; j < 5; j++)
                s += v5[j] * __ldg(&W2[(size_t)jj * KP2P + (oc0 + j) * 25 + pos]);
            hd[jj] = s;
        }
    }
    // block reduce 12 sums
    const int lane = tid & 31, wrp = tid >> 5;
    #pragma unroll
    for (int jj = 0; jj < 12; jj++) {
        #pragma unroll
        for (int off = 16; off; off >>= 1)
            hd[jj] += __shfl_xor_sync(0xffffffffu, hd[jj], off);
    }
    if (lane == 0) {
        #pragma unroll
        for (int jj = 0; jj < 12; jj++) red[jj * 8 + wrp] = hd[jj];
    }
    __syncthreads();
    if (tid < 12) {
        float s = __ldg(&b2c[tid]);
        #pragma unroll
        for (int w = 0; w < 8; w++) s += red[tid * 8 + w];
        red[96 + tid] = s;
    }
    __syncthreads();

    const float em0 = red[96 + 10], em1 = red[96 + 11];
    if (tid == 0) e2[b] = (em0 >= em1) ? 1 : 0;
    if (tid < 10) o2[b * 10 + tid] = red[96 + tid];
    if (em0 >= em1) return;    // uniform: exit at stage 2, no conv3 needed

    // ---- fused conv3: h2s (smem) -> f3 ----
    if (tid < 250) {
        const int oc2 = tid % 50, grp = tid / 50;
        const float* w3 = c3_w + oc2 * 450 + grp * 90;
        float a0 = 0.f, a1 = 0.f, a2 = 0.f, a3 = 0.f;
        #pragma unroll
        for (int i2 = 0; i2 < 10; i2++) {
            const float* hc = h2s + (grp * 10 + i2) * 25;
            #pragma unroll
            for (int ky = 0; ky < 3; ky++)
                #pragma unroll
                for (int kx = 0; kx < 3; kx++) {
                    float wv = __ldg(&w3[i2 * 9 + ky * 3 + kx]);
                    a0 += hc[ky * 5 + kx] * wv;
                    a1 += hc[ky * 5 + kx + 1] * wv;
                    a2 += hc[(ky + 1) * 5 + kx] * wv;
                    a3 += hc[(ky + 1) * 5 + kx + 1] * wv;
                }
        }
        float* r3 = red3 + grp * 200 + oc2 * 4;
        r3[0] = a0; r3[1] = a1; r3[2] = a2; r3[3] = a3;
    }
    __syncthreads();
    if (tid < 50) {
        float a0 = 0.f, a1 = 0.f, a2 = 0.f, a3 = 0.f;
        #pragma unroll
        for (int g = 0; g < 5; g++) {
            const float* r3 = red3 + g * 200 + tid * 4;
            a0 += r3[0]; a1 += r3[1]; a2 += r3[2]; a3 += r3[3];
        }
        float m = fmaxf(fmaxf(a0, a1), fmaxf(a2, a3)) + __ldg(&c3_b[tid]);
        f3[b * 50 + tid] = fmaxf(m, 0.f);
    }
}

// ==== stage3 + final fused ===================================================
#define S3_G 32
#define S3_SMEM ((25000 + 5000 + 500 + S3_G * 50 + S3_G * 500 + S3_G * 10) * 4)

__global__ __launch_bounds__(256) void stage3final_kernel(
    const float* __restrict__ f3,
    const float* __restrict__ l1w, const float* __restrict__ l1b,
    const float* __restrict__ l2w, const float* __restrict__ l2b,
    const int* __restrict__ e1, const int* __restrict__ e2,
    const float* __restrict__ part, const float* __restrict__ b1c,
    const float* __restrict__ o2, float* __restrict__ out)
{
    extern __shared__ __align__(16) float sm[];
    float* w1  = sm;
    float* w2  = sm + 25000;
    float* b1  = sm + 30000;
    float* fs  = sm + 30500;
    float* hid = sm + 32100;
    float* o3s = sm + 48100;
    int tid = threadIdx.x;
    int b0 = blockIdx.x * S3_G;

    for (int i = tid; i < 25000; i += 256) w1[i] = l1w[i];
    for (int i = tid; i < 5000;  i += 256) w2[i] = l2w[i];
    for (int i = tid; i < 500;   i += 256) b1[i] = l1b[i];
    for (int i = tid; i < S3_G * 50; i += 256) fs[i] = f3[b0 * 50 + i];
    __syncthreads();

    for (int hh = tid; hh < S3_G * 500; hh += 256) {
        int s = hh / 500, j = hh - s * 500;
        float a = b1[j];
        const float* fr = fs + s * 50;
        const float* wr = w1 + j * 50;
        #pragma unroll 10
        for (int k = 0; k < 50; k++) a += fr[k] * wr[k];
        hid[hh] = fmaxf(a, 0.f);
    }
    __syncthreads();

    for (int oo = tid; oo < S3_G * 10; oo += 256) {
        int s = oo / 10, n = oo - s * 10;
        float a = __ldg(&l2b[n]);
        const float* hr = hid + s * 500;
        const float* wr = w2 + n * 500;
        #pragma unroll 4
        for (int j = 0; j < 500; j++) a += hr[j] * wr[j];
        o3s[s * 10 + n] = a;
    }
    __syncthreads();

    if (tid < S3_G) {
        int b = b0 + tid;
        float v[10];
        if (e1[b]) {
            #pragma unroll
            for (int j = 0; j < 10; j++)
                v[j] = part[b * 24 + j] + part[b * 24 + 12 + j] + __ldg(&b1c[j]);
        } else if (e2[b]) {
            #pragma unroll
            for (int j = 0; j < 10; j++) v[j] = o2[b * 10 + j];
        } else {
            #pragma unroll
            for (int j = 0; j < 10; j++) v[j] = o3s[tid * 10 + j];
        }
        float mx = -1e30f;
        #pragma unroll
        for (int j = 0; j < 10; j++) mx = fmaxf(mx, v[j]);
        float sum = 0.f;
        #pragma unroll
        for (int j = 0; j < 10; j++) sum += expf(v[j] - mx);
        float l = logf(sum);
        #pragma unroll
        for (int j = 0; j < 10; j++) out[b * 10 + j] = v[j] - mx - l;
    }
}

// ---------------- launch ----------------------------------------------------
extern "C" void kernel_launch(void* const* d_in, const int* in_sizes, int n_in,
                              void* d_out, int out_size)
{
    const float* x      = (const float*)d_in[0];
    const float* c1_w   = (const float*)d_in[1];
    const float* c1_b   = (const float*)d_in[2];
    const float* c2_w   = (const float*)d_in[3];
    const float* c2_b   = (const float*)d_in[4];
    const float* c3_w   = (const float*)d_in[5];
    const float* c3_b   = (const float*)d_in[6];
    const float* l1c1_w = (const float*)d_in[7];
    const float* l1c1_b = (const float*)d_in[8];
    const float* l2c1_w = (const float*)d_in[9];
    const float* l2c1_b = (const float*)d_in[10];
    const float* l1c2_w = (const float*)d_in[11];
    const float* l1c2_b = (const float*)d_in[12];
    const float* l2c2_w = (const float*)d_in[13];
    const float* l2c2_b = (const float*)d_in[14];
    const float* l1_w   = (const float*)d_in[15];
    const float* l1_b   = (const float*)d_in[16];
    const float* l2_w   = (const float*)d_in[17];
    const float* l2_b   = (const float*)d_in[18];
    const float* d1_w   = (const float*)d_in[19];
    const float* d1_b   = (const float*)d_in[20];
    const float* d2_w   = (const float*)d_in[21];
    const float* d2_b   = (const float*)d_in[22];
    float* out = (float*)d_out;

    float *h1, *f3, *o2, *W1, *W2, *b1c, *b2c, *part1;
    float2 *wpk2;
    int *e1, *e2;
    cudaGetSymbolAddress((void**)&h1,   g_h1);
    cudaGetSymbolAddress((void**)&f3,   g_f3);
    cudaGetSymbolAddress((void**)&o2,   g_o2);
    cudaGetSymbolAddress((void**)&e1,   g_e1);
    cudaGetSymbolAddress((void**)&e2,   g_e2);
    cudaGetSymbolAddress((void**)&W1,   g_W1);
    cudaGetSymbolAddress((void**)&W2,   g_W2);
    cudaGetSymbolAddress((void**)&b1c,  g_b1c);
    cudaGetSymbolAddress((void**)&b2c,  g_b2c);
    cudaGetSymbolAddress((void**)&part1, g_part1);
    cudaGetSymbolAddress((void**)&wpk2, g_wpk2);

    static cudaStream_t s2 = nullptr;
    static cudaEvent_t evA = nullptr, evB = nullptr;
    static int attr_set = 0;
    if (!attr_set) {
        cudaFuncSetAttribute(conv2_kernel,
                             cudaFuncAttributeMaxDynamicSharedMemorySize, C2_SMEM);
        cudaFuncSetAttribute(stage3final_kernel,
                             cudaFuncAttributeMaxDynamicSharedMemorySize, S3_SMEM);
        cudaStreamCreateWithFlags(&s2, cudaStreamNonBlocking);
        cudaEventCreateWithFlags(&evA, cudaEventDisableTiming);
        cudaEventCreateWithFlags(&evB, cudaEventDisableTiming);
        attr_set = 1;
    }

    // fork: prep on side stream, conv1 on main stream (independent)
    cudaEventRecord(evA, 0);
    cudaStreamWaitEvent(s2, evA, 0);
    prep_kernel<<<128, 256, 0, s2>>>(l1c1_w, l1c1_b, l2c1_w, l2c1_b,
                                     l1c2_w, l1c2_b, l2c2_w, l2c2_b,
                                     d1_w, d1_b, d2_w, d2_b, c2_w,
                                     W1, b1c, W2, b2c, wpk2);
    cudaEventRecord(evB, s2);

    conv1_kernel<<<BATCH, 192>>>(x, c1_w, c1_b, h1);

    // join: sh1 needs W1 (prep) + h1 (conv1)
    cudaStreamWaitEvent(0, evB, 0);
    stagehead_part_kernel<<<dim3(BATCH / 16, 2), 256>>>(h1, KP1P, W1, part1);

    // stage 2+3 mega: conv2 + head (e1/e2/o2) + conv3 (f3), h2 stays in smem
    conv2_kernel<<<BATCH, 256, C2_SMEM>>>(h1, wpk2, c2_b, part1, b1c,
                                          W2, b2c, c3_w, c3_b, e1, e2, o2, f3);

    // stage 3 MLP + final select/log_softmax
    stage3final_kernel<<<BATCH / S3_G, 256, S3_SMEM>>>(
        f3, l1_w, l1_b, l2_w, l2_b, e1, e2, part1, b1c, o2, out);
}

// round 14
// speedup vs baseline: 1.0465x; 1.0387x over previous
#include <cuda_runtime.h>
#include <math.h>
#include <stdint.h>

#define BATCH 4096
#define HALF 2048
#define K1 8450
#define K2 1250
#define KP1P 8704          // h1 row pitch (17 * 512)
#define KP2P 1536          // W2 row pitch

// ---------------- scratch (device globals; zero-initialized) ---------------
__device__ float g_h1[(size_t)BATCH * KP1P];
__device__ float g_f3[BATCH * 50];
__device__ float g_o2[BATCH * 10];
__device__ int   g_e1[BATCH];
__device__ int   g_e2[BATCH];
__device__ float g_W1[12 * KP1P];    // rows 0-9: l2c1@l1c1; 10-11: d1_w
__device__ float g_W2[12 * KP2P];
__device__ float g_b1c[12];
__device__ float g_b2c[12];
__device__ float g_part1[BATCH * 24];  // [b][split(2)][12]
__device__ float2 g_wpk2[50 * 500];    // conv2 weights [ic][oc][10] dup, pad k=9 zero

// ================= merged prep kernel =======================================
__device__ void combine_part(
    const float* __restrict__ l1, const float* __restrict__ b1,
    const float* __restrict__ l2, const float* __restrict__ b2,
    const float* __restrict__ dw, const float* __restrict__ db,
    int K, int Kp, float* __restrict__ W12, float* __restrict__ bc12,
    int blk, float* l2T)
{
    int tid = threadIdx.x;
    for (int i = tid; i < 5000; i += 256) {
        int j = i / 500, r = i - j * 500;
        l2T[r * 12 + j] = l2[i];
    }
    for (int r = tid; r < 500; r += 256) { l2T[r * 12 + 10] = 0.f; l2T[r * 12 + 11] = 0.f; }
    __syncthreads();

    int k = blk * 256 + tid;
    if (k < Kp) {
        if (k < K) {
            float acc[10];
            #pragma unroll
            for (int j = 0; j < 10; j++) acc[j] = 0.f;
            #pragma unroll 4
            for (int r = 0; r < 500; r++) {
                float a = __ldg(&l1[(size_t)r * K + k]);
                float4 w0 = *(const float4*)&l2T[r * 12];
                float4 w1 = *(const float4*)&l2T[r * 12 + 4];
                float2 w2 = *(const float2*)&l2T[r * 12 + 8];
                acc[0] += a * w0.x; acc[1] += a * w0.y; acc[2] += a * w0.z; acc[3] += a * w0.w;
                acc[4] += a * w1.x; acc[5] += a * w1.y; acc[6] += a * w1.z; acc[7] += a * w1.w;
                acc[8] += a * w2.x; acc[9] += a * w2.y;
            }
            #pragma unroll
            for (int j = 0; j < 10; j++) W12[(size_t)j * Kp + k] = acc[j];
            W12[(size_t)10 * Kp + k] = __ldg(&dw[k]);
            W12[(size_t)11 * Kp + k] = __ldg(&dw[K + k]);
        } else {
            #pragma unroll
            for (int j = 0; j < 12; j++) W12[(size_t)j * Kp + k] = 0.f;
        }
    }
    if (blk == 0) {
        if (tid < 10) {
            float a = b2[tid];
            for (int r = 0; r < 500; r++) a += l2[tid * 500 + r] * b1[r];
            bc12[tid] = a;
        } else if (tid < 12) {
            bc12[tid] = db[tid - 10];
        }
    }
}

__global__ __launch_bounds__(256) void prep_kernel(
    const float* l1c1_w, const float* l1c1_b, const float* l2c1_w, const float* l2c1_b,
    const float* l1c2_w, const float* l1c2_b, const float* l2c2_w, const float* l2c2_b,
    const float* d1_w, const float* d1_b, const float* d2_w, const float* d2_b,
    const float* c2_w,
    float* W1, float* b1c, float* W2, float* b2c, float2* wpk2)
{
    __shared__ __align__(16) float l2T[500 * 12];
    int bx = blockIdx.x, tid = threadIdx.x;
    if (bx < 34) {
        combine_part(l1c1_w, l1c1_b, l2c1_w, l2c1_b, d1_w, d1_b, K1, KP1P, W1, b1c, bx, l2T);
    } else if (bx < 40) {
        combine_part(l1c2_w, l1c2_b, l2c2_w, l2c2_b, d2_w, d2_b, K2, KP2P, W2, b2c, bx - 34, l2T);
    } else {
        int i = (bx - 40) * 256 + tid;
        if (i < 22500) {
            int oc = i / 450, r = i - oc * 450;
            int ic = r / 9, k = r - ic * 9;
            float v = c2_w[i];
            wpk2[ic * 500 + oc * 10 + k] = make_float2(v, v);   // pad k=9 stays zero
        }
    }
}

// ---------------- conv1: register patch + packed f32x2 ----------------------
__global__ __launch_bounds__(192) void conv1_kernel(
    const float* __restrict__ x, const float* __restrict__ w,
    const float* __restrict__ bias, float* __restrict__ h1, int bbase)
{
    int b = bbase + blockIdx.x;
    __shared__ __align__(16) float xs[784];
    __shared__ __align__(16) float2 ws[450];
    __shared__ __align__(16) float bs[50];
    int tid = threadIdx.x;
    {
        const float4* xb = (const float4*)(x + (size_t)b * 784);
        for (int i = tid; i < 196; i += 192) ((float4*)xs)[i] = xb[i];
        for (int i = tid; i < 450; i += 192) { float v = w[i]; ws[i] = make_float2(v, v); }
        for (int i = tid; i < 50;  i += 192) bs[i] = bias[i];
    }
    __syncthreads();
    if (tid >= 169) return;

    const int py = tid / 13, px = tid % 13;
    const int Y = 2 * py, X = 2 * px;
    float p[4][4];
    #pragma unroll
    for (int r = 0; r < 4; r++)
        #pragma unroll
        for (int c = 0; c < 4; c++) p[r][c] = xs[(Y + r) * 28 + X + c];
    unsigned long long P[4][3];
    #pragma unroll
    for (int r = 0; r < 4; r++)
        #pragma unroll
        for (int k = 0; k < 3; k++)
            asm("mov.b64 %0, {%1, %2};" : "=l"(P[r][k])
                : "r"(__float_as_uint(p[r][k])), "r"(__float_as_uint(p[r][k + 1])));

    float* hb = h1 + (size_t)b * KP1P + tid;
    for (int oc = 0; oc < 50; oc++) {
        unsigned long long aT = 0ULL, aB = 0ULL;
        #pragma unroll
        for (int ky = 0; ky < 3; ky++)
            #pragma unroll
            for (int kx = 0; kx < 3; kx++) {
                unsigned long long w2 = *(const unsigned long long*)&ws[oc * 9 + ky * 3 + kx];
                asm("fma.rn.f32x2 %0, %1, %2, %0;" : "+l"(aT) : "l"(P[ky][kx]), "l"(w2));
                asm("fma.rn.f32x2 %0, %1, %2, %0;" : "+l"(aB) : "l"(P[ky + 1][kx]), "l"(w2));
            }
        unsigned int u0, u1, u2, u3;
        asm("mov.b64 {%0, %1}, %2;" : "=r"(u0), "=r"(u1) : "l"(aT));
        asm("mov.b64 {%0, %1}, %2;" : "=r"(u2), "=r"(u3) : "l"(aB));
        float m = fmaxf(fmaxf(__uint_as_float(u0), __uint_as_float(u1)),
                        fmaxf(__uint_as_float(u2), __uint_as_float(u3)));
        m += bs[oc];
        hb[oc * 169] = fmaxf(m, 0.f);
    }
}

// ====== stagehead (stage 1): direct-LDG streamer, no smem, no barriers ======
__global__ __launch_bounds__(256) void stagehead_part_kernel(
    const float* __restrict__ f, int Kp,
    const float* __restrict__ W12, float* __restrict__ part, int bbase)
{
    const int tid = threadIdx.x, lane = tid & 31, wid = tid >> 5;
    const int b0 = bbase + blockIdx.x * 16;
    const int split = blockIdx.y;
    const int s0 = b0 + wid * 2, s1 = s0 + 1;
    const int half = Kp >> 1;
    const int kBeg = split * half;
    const int kEnd = kBeg + half;

    float acc0[12], acc1[12];
    #pragma unroll
    for (int j = 0; j < 12; j++) { acc0[j] = 0.f; acc1[j] = 0.f; }

    const float* f0p = f + (size_t)s0 * Kp;
    const float* f1p = f + (size_t)s1 * Kp;

    #pragma unroll 2
    for (int k = kBeg + lane * 4; k < kEnd; k += 128) {
        float4 a0 = *(const float4*)(f0p + k);
        float4 a1 = *(const float4*)(f1p + k);
        #pragma unroll
        for (int j = 0; j < 12; j++) {
            float4 w = __ldg((const float4*)&W12[(size_t)j * Kp + k]);
            acc0[j] = fmaf(a0.x, w.x, fmaf(a0.y, w.y, fmaf(a0.z, w.z, fmaf(a0.w, w.w, acc0[j]))));
            acc1[j] = fmaf(a1.x, w.x, fmaf(a1.y, w.y, fmaf(a1.z, w.z, fmaf(a1.w, w.w, acc1[j]))));
        }
    }

    #pragma unroll
    for (int j = 0; j < 12; j++) {
        #pragma unroll
        for (int off = 16; off; off >>= 1) {
            acc0[j] += __shfl_xor_sync(0xffffffffu, acc0[j], off);
            acc1[j] += __shfl_xor_sync(0xffffffffu, acc1[j], off);
        }
    }
    if (lane == 0) {
        #pragma unroll
        for (int j = 0; j < 12; j++) {
            part[s0 * 24 + split * 12 + j] = acc0[j];
            part[s1 * 24 + split * 12 + j] = acc1[j];
        }
    }
}

// ====== conv2 mega: conv2 + stage-2 head + conv3, double-buffered weights ===
#define C2_SMEM 86064
__global__ __launch_bounds__(256, 2) void conv2_kernel(
    const float* __restrict__ h1, const float2* __restrict__ wpk,
    const float* __restrict__ bias, const float* __restrict__ part,
    const float* __restrict__ b1c,
    const float* __restrict__ W2, const float* __restrict__ b2c,
    const float* __restrict__ c3_w, const float* __restrict__ c3_b,
    int* __restrict__ e1, int* __restrict__ e2,
    float* __restrict__ o2, float* __restrict__ f3, int bbase)
{
    extern __shared__ __align__(16) char csm[];
    float*  hs   = (float*)csm;
    float2* wb   = (float2*)(csm + 36416);
    float*  h2s  = (float*)(csm + 76416);
    float*  bss  = (float*)(csm + 81416);
    float*  red  = (float*)(csm + 81616);
    float*  red3 = (float*)(csm + 82064);
    __shared__ int sflag;

    const int b = bbase + blockIdx.x;
    const int tid = threadIdx.x;
    if (tid == 0) {
        float m0 = part[b * 24 + 10] + part[b * 24 + 22] + __ldg(&b1c[10]);
        float m1 = part[b * 24 + 11] + part[b * 24 + 23] + __ldg(&b1c[11]);
        int fl = (m0 >= m1) ? 1 : 0;
        e1[b] = fl;
        sflag = fl;
        if (fl) e2[b] = 0;     // deterministic; unused when e1 selected
    }
    __syncthreads();
    if (sflag) return;

    {
        const float* hb = h1 + (size_t)b * KP1P;
        for (int i = tid; i < 8450; i += 256) {
            int ic = i / 169, rem = i - ic * 169;
            int r = rem / 13, c = rem - r * 13;
            hs[ic * 182 + r * 14 + c] = hb[i];
        }
        for (int i = tid; i < 50; i += 256) bss[i] = bias[i];
        for (int i = tid; i < 1250; i += 256)
            ((float4*)wb)[i] = ((const float4*)wpk)[i];
    }
    __syncthreads();

    const int osub = tid / 25, pos = tid % 25;
    const int oc0 = osub * 5;
    const int py = pos / 5, px = pos % 5;
    const int Y = 2 * py, X = 2 * px;
    const bool active = (tid < 250);

    unsigned long long aT[5], aB[5];
    #pragma unroll
    for (int j = 0; j < 5; j++) { aT[j] = 0ULL; aB[j] = 0ULL; }

    for (int t = 0; t < 10; t++) {
        const int cur = t & 1;
        if (t + 1 < 10) {
            const float4* src = (const float4*)wpk + (t + 1) * 1250;
            float4* dst = (float4*)(wb + (cur ^ 1) * 2500);
            for (int i = tid; i < 1250; i += 256) dst[i] = src[i];
        }
        if (active) {
            #pragma unroll
            for (int i5 = 0; i5 < 5; i5++) {
                const float* hc = hs + (t * 5 + i5) * 182;
                unsigned long long P[4][3];
                #pragma unroll
                for (int r = 0; r < 4; r++) {
                    float2 v0 = *(const float2*)(hc + (Y + r) * 14 + X);
                    float2 v1 = *(const float2*)(hc + (Y + r) * 14 + X + 2);
                    asm("mov.b64 %0, {%1, %2};" : "=l"(P[r][0])
                        : "r"(__float_as_uint(v0.x)), "r"(__float_as_uint(v0.y)));
                    asm("mov.b64 %0, {%1, %2};" : "=l"(P[r][1])
                        : "r"(__float_as_uint(v0.y)), "r"(__float_as_uint(v1.x)));
                    asm("mov.b64 %0, {%1, %2};" : "=l"(P[r][2])
                        : "r"(__float_as_uint(v1.x)), "r"(__float_as_uint(v1.y)));
                }
                const float2* wrow = wb + cur * 2500 + (i5 * 50 + oc0) * 10;
                #pragma unroll
                for (int j = 0; j < 5; j++) {
                    const float2* wp = wrow + j * 10;
                    ulonglong2 q0 = *(const ulonglong2*)(wp);
                    ulonglong2 q1 = *(const ulonglong2*)(wp + 2);
                    ulonglong2 q2 = *(const ulonglong2*)(wp + 4);
                    ulonglong2 q3 = *(const ulonglong2*)(wp + 6);
                    unsigned long long w8 = *(const unsigned long long*)(wp + 8);
                    unsigned long long wv[9] = {q0.x, q0.y, q1.x, q1.y,
                                                q2.x, q2.y, q3.x, q3.y, w8};
                    #pragma unroll
                    for (int ky = 0; ky < 3; ky++)
                        #pragma unroll
                        for (int kx = 0; kx < 3; kx++) {
                            asm("fma.rn.f32x2 %0, %1, %2, %0;"
                                : "+l"(aT[j]) : "l"(P[ky][kx]), "l"(wv[ky * 3 + kx]));
                            asm("fma.rn.f32x2 %0, %1, %2, %0;"
                                : "+l"(aB[j]) : "l"(P[ky + 1][kx]), "l"(wv[ky * 3 + kx]));
                        }
                }
            }
        }
        __syncthreads();
    }

    float hd[12];
    #pragma unroll
    for (int jj = 0; jj < 12; jj++) hd[jj] = 0.f;
    if (active) {
        float v5[5];
        #pragma unroll
        for (int j = 0; j < 5; j++) {
            unsigned int u0, u1, u2, u3;
            asm("mov.b64 {%0, %1}, %2;" : "=r"(u0), "=r"(u1) : "l"(aT[j]));
            asm("mov.b64 {%0, %1}, %2;" : "=r"(u2), "=r"(u3) : "l"(aB[j]));
            float m = fmaxf(fmaxf(__uint_as_float(u0), __uint_as_float(u1)),
                            fmaxf(__uint_as_float(u2), __uint_as_float(u3)));
            m += bss[oc0 + j];
            v5[j] = fmaxf(m, 0.f);
            h2s[(oc0 + j) * 25 + pos] = v5[j];
        }
        #pragma unroll
        for (int jj = 0; jj < 12; jj++) {
            float s = 0.f;
            #pragma unroll
            for (int j = 0; j < 5; j++)
                s += v5[j] * __ldg(&W2[(size_t)jj * KP2P + (oc0 + j) * 25 + pos]);
            hd[jj] = s;
        }
    }
    const int lane = tid & 31, wrp = tid >> 5;
    #pragma unroll
    for (int jj = 0; jj < 12; jj++) {
        #pragma unroll
        for (int off = 16; off; off >>= 1)
            hd[jj] += __shfl_xor_sync(0xffffffffu, hd[jj], off);
    }
    if (lane == 0) {
        #pragma unroll
        for (int jj = 0; jj < 12; jj++) red[jj * 8 + wrp] = hd[jj];
    }
    __syncthreads();
    if (tid < 12) {
        float s = __ldg(&b2c[tid]);
        #pragma unroll
        for (int w = 0; w < 8; w++) s += red[tid * 8 + w];
        red[96 + tid] = s;
    }
    __syncthreads();

    const float em0 = red[96 + 10], em1 = red[96 + 11];
    if (tid == 0) e2[b] = (em0 >= em1) ? 1 : 0;
    if (tid < 10) o2[b * 10 + tid] = red[96 + tid];
    if (em0 >= em1) return;

    // ---- fused conv3: h2s (smem) -> f3 ----
    if (tid < 250) {
        const int oc2 = tid % 50, grp = tid / 50;
        const float* w3 = c3_w + oc2 * 450 + grp * 90;
        float a0 = 0.f, a1 = 0.f, a2 = 0.f, a3 = 0.f;
        #pragma unroll
        for (int i2 = 0; i2 < 10; i2++) {
            const float* hc = h2s + (grp * 10 + i2) * 25;
            #pragma unroll
            for (int ky = 0; ky < 3; ky++)
                #pragma unroll
                for (int kx = 0; kx < 3; kx++) {
                    float wv = __ldg(&w3[i2 * 9 + ky * 3 + kx]);
                    a0 += hc[ky * 5 + kx] * wv;
                    a1 += hc[ky * 5 + kx + 1] * wv;
                    a2 += hc[(ky + 1) * 5 + kx] * wv;
                    a3 += hc[(ky + 1) * 5 + kx + 1] * wv;
                }
        }
        float* r3 = red3 + grp * 200 + oc2 * 4;
        r3[0] = a0; r3[1] = a1; r3[2] = a2; r3[3] = a3;
    }
    __syncthreads();
    if (tid < 50) {
        float a0 = 0.f, a1 = 0.f, a2 = 0.f, a3 = 0.f;
        #pragma unroll
        for (int g = 0; g < 5; g++) {
            const float* r3 = red3 + g * 200 + tid * 4;
            a0 += r3[0]; a1 += r3[1]; a2 += r3[2]; a3 += r3[3];
        }
        float m = fmaxf(fmaxf(a0, a1), fmaxf(a2, a3)) + __ldg(&c3_b[tid]);
        f3[b * 50 + tid] = fmaxf(m, 0.f);
    }
}

// ==== stage3 + final fused ===================================================
#define S3_G 32
#define S3_SMEM ((25000 + 5000 + 500 + S3_G * 50 + S3_G * 500 + S3_G * 10) * 4)

__global__ __launch_bounds__(256) void stage3final_kernel(
    const float* __restrict__ f3,
    const float* __restrict__ l1w, const float* __restrict__ l1b,
    const float* __restrict__ l2w, const float* __restrict__ l2b,
    const int* __restrict__ e1, const int* __restrict__ e2,
    const float* __restrict__ part, const float* __restrict__ b1c,
    const float* __restrict__ o2, float* __restrict__ out, int bbase)
{
    extern __shared__ __align__(16) float sm[];
    float* w1  = sm;
    float* w2  = sm + 25000;
    float* b1  = sm + 30000;
    float* fs  = sm + 30500;
    float* hid = sm + 32100;
    float* o3s = sm + 48100;
    int tid = threadIdx.x;
    int b0 = bbase + blockIdx.x * S3_G;

    for (int i = tid; i < 25000; i += 256) w1[i] = l1w[i];
    for (int i = tid; i < 5000;  i += 256) w2[i] = l2w[i];
    for (int i = tid; i < 500;   i += 256) b1[i] = l1b[i];
    for (int i = tid; i < S3_G * 50; i += 256) fs[i] = f3[b0 * 50 + i];
    __syncthreads();

    for (int hh = tid; hh < S3_G * 500; hh += 256) {
        int s = hh / 500, j = hh - s * 500;
        float a = b1[j];
        const float* fr = fs + s * 50;
        const float* wr = w1 + j * 50;
        #pragma unroll 10
        for (int k = 0; k < 50; k++) a += fr[k] * wr[k];
        hid[hh] = fmaxf(a, 0.f);
    }
    __syncthreads();

    for (int oo = tid; oo < S3_G * 10; oo += 256) {
        int s = oo / 10, n = oo - s * 10;
        float a = __ldg(&l2b[n]);
        const float* hr = hid + s * 500;
        const float* wr = w2 + n * 500;
        #pragma unroll 4
        for (int j = 0; j < 500; j++) a += hr[j] * wr[j];
        o3s[s * 10 + n] = a;
    }
    __syncthreads();

    if (tid < S3_G) {
        int b = b0 + tid;
        float v[10];
        if (e1[b]) {
            #pragma unroll
            for (int j = 0; j < 10; j++)
                v[j] = part[b * 24 + j] + part[b * 24 + 12 + j] + __ldg(&b1c[j]);
        } else if (e2[b]) {
            #pragma unroll
            for (int j = 0; j < 10; j++) v[j] = o2[b * 10 + j];
        } else {
            #pragma unroll
            for (int j = 0; j < 10; j++) v[j] = o3s[tid * 10 + j];
        }
        float mx = -1e30f;
        #pragma unroll
        for (int j = 0; j < 10; j++) mx = fmaxf(mx, v[j]);
        float sum = 0.f;
        #pragma unroll
        for (int j = 0; j < 10; j++) sum += expf(v[j] - mx);
        float l = logf(sum);
        #pragma unroll
        for (int j = 0; j < 10; j++) out[b * 10 + j] = v[j] - mx - l;
    }
}

// ---------------- launch ----------------------------------------------------
extern "C" void kernel_launch(void* const* d_in, const int* in_sizes, int n_in,
                              void* d_out, int out_size)
{
    const float* x      = (const float*)d_in[0];
    const float* c1_w   = (const float*)d_in[1];
    const float* c1_b   = (const float*)d_in[2];
    const float* c2_w   = (const float*)d_in[3];
    const float* c2_b   = (const float*)d_in[4];
    const float* c3_w   = (const float*)d_in[5];
    const float* c3_b   = (const float*)d_in[6];
    const float* l1c1_w = (const float*)d_in[7];
    const float* l1c1_b = (const float*)d_in[8];
    const float* l2c1_w = (const float*)d_in[9];
    const float* l2c1_b = (const float*)d_in[10];
    const float* l1c2_w = (const float*)d_in[11];
    const float* l1c2_b = (const float*)d_in[12];
    const float* l2c2_w = (const float*)d_in[13];
    const float* l2c2_b = (const float*)d_in[14];
    const float* l1_w   = (const float*)d_in[15];
    const float* l1_b   = (const float*)d_in[16];
    const float* l2_w   = (const float*)d_in[17];
    const float* l2_b   = (const float*)d_in[18];
    const float* d1_w   = (const float*)d_in[19];
    const float* d1_b   = (const float*)d_in[20];
    const float* d2_w   = (const float*)d_in[21];
    const float* d2_b   = (const float*)d_in[22];
    float* out = (float*)d_out;

    float *h1, *f3, *o2, *W1, *W2, *b1c, *b2c, *part1;
    float2 *wpk2;
    int *e1, *e2;
    cudaGetSymbolAddress((void**)&h1,   g_h1);
    cudaGetSymbolAddress((void**)&f3,   g_f3);
    cudaGetSymbolAddress((void**)&o2,   g_o2);
    cudaGetSymbolAddress((void**)&e1,   g_e1);
    cudaGetSymbolAddress((void**)&e2,   g_e2);
    cudaGetSymbolAddress((void**)&W1,   g_W1);
    cudaGetSymbolAddress((void**)&W2,   g_W2);
    cudaGetSymbolAddress((void**)&b1c,  g_b1c);
    cudaGetSymbolAddress((void**)&b2c,  g_b2c);
    cudaGetSymbolAddress((void**)&part1, g_part1);
    cudaGetSymbolAddress((void**)&wpk2, g_wpk2);

    static cudaStream_t s2 = nullptr, s3 = nullptr;
    static cudaEvent_t evA = nullptr, evP = nullptr, evC = nullptr;
    static int attr_set = 0;
    if (!attr_set) {
        cudaFuncSetAttribute(conv2_kernel,
                             cudaFuncAttributeMaxDynamicSharedMemorySize, C2_SMEM);
        cudaFuncSetAttribute(stage3final_kernel,
                             cudaFuncAttributeMaxDynamicSharedMemorySize, S3_SMEM);
        cudaStreamCreateWithFlags(&s2, cudaStreamNonBlocking);
        cudaStreamCreateWithFlags(&s3, cudaStreamNonBlocking);
        cudaEventCreateWithFlags(&evA, cudaEventDisableTiming);
        cudaEventCreateWithFlags(&evP, cudaEventDisableTiming);
        cudaEventCreateWithFlags(&evC, cudaEventDisableTiming);
        attr_set = 1;
    }

    // fork both side streams from main
    cudaEventRecord(evA, 0);
    cudaStreamWaitEvent(s2, evA, 0);
    cudaStreamWaitEvent(s3, evA, 0);

    // prep on s2
    prep_kernel<<<128, 256, 0, s2>>>(l1c1_w, l1c1_b, l2c1_w, l2c1_b,
                                     l1c2_w, l1c2_b, l2c2_w, l2c2_b,
                                     d1_w, d1_b, d2_w, d2_b, c2_w,
                                     W1, b1c, W2, b2c, wpk2);
    cudaEventRecord(evP, s2);

    // chain 0 on main (half 0), chain 1 on s3 (half 1)
    conv1_kernel<<<HALF, 192>>>(x, c1_w, c1_b, h1, 0);
    conv1_kernel<<<HALF, 192, 0, s3>>>(x, c1_w, c1_b, h1, HALF);

    cudaStreamWaitEvent(0, evP, 0);
    cudaStreamWaitEvent(s3, evP, 0);

    stagehead_part_kernel<<<dim3(HALF / 16, 2), 256>>>(h1, KP1P, W1, part1, 0);
    stagehead_part_kernel<<<dim3(HALF / 16, 2), 256, 0, s3>>>(h1, KP1P, W1, part1, HALF);

    conv2_kernel<<<HALF, 256, C2_SMEM>>>(h1, wpk2, c2_b, part1, b1c,
                                         W2, b2c, c3_w, c3_b, e1, e2, o2, f3, 0);
    conv2_kernel<<<HALF, 256, C2_SMEM, s3>>>(h1, wpk2, c2_b, part1, b1c,
                                             W2, b2c, c3_w, c3_b, e1, e2, o2, f3, HALF);

    stage3final_kernel<<<HALF / S3_G, 256, S3_SMEM>>>(
        f3, l1_w, l1_b, l2_w, l2_b, e1, e2, part1, b1c, o2, out, 0);
    stage3final_kernel<<<HALF / S3_G, 256, S3_SMEM, s3>>>(
        f3, l1_w, l1_b, l2_w, l2_b, e1, e2, part1, b1c, o2, out, HALF);

    // join chain 1 back into main
    cudaEventRecord(evC, s3);
    cudaStreamWaitEvent(0, evC, 0);
}

// round 15
// speedup vs baseline: 1.0961x; 1.0474x over previous
#include <cuda_runtime.h>
#include <math.h>
#include <stdint.h>

#define BATCH 4096
#define HALF 2048
#define K1 8450
#define K2 1250
#define KP1P 8704          // h1 row pitch (17 * 512)
#define KP2P 1536          // W2 row pitch

// ---------------- scratch (device globals; zero-initialized) ---------------
__device__ float g_h1[(size_t)BATCH * KP1P];
__device__ float g_f3[BATCH * 50];
__device__ float g_o2[BATCH * 10];
__device__ int   g_e1[BATCH];
__device__ int   g_e2[BATCH];
__device__ float g_W1[12 * KP1P];    // rows 0-9: l2c1@l1c1; 10-11: d1_w
__device__ float g_W2[12 * KP2P];
__device__ float g_b1c[12];
__device__ float g_b2c[12];
__device__ float g_part1[BATCH * 24];  // [b][split(2)][12]
__device__ float2 g_wpk2[50 * 500];    // conv2 weights [ic][oc][10] dup, pad k=9 zero

// ================= merged prep kernel =======================================
__device__ void combine_part(
    const float* __restrict__ l1, const float* __restrict__ b1,
    const float* __restrict__ l2, const float* __restrict__ b2,
    const float* __restrict__ dw, const float* __restrict__ db,
    int K, int Kp, float* __restrict__ W12, float* __restrict__ bc12,
    int blk, float* l2T)
{
    int tid = threadIdx.x;
    for (int i = tid; i < 5000; i += 256) {
        int j = i / 500, r = i - j * 500;
        l2T[r * 12 + j] = l2[i];
    }
    for (int r = tid; r < 500; r += 256) { l2T[r * 12 + 10] = 0.f; l2T[r * 12 + 11] = 0.f; }
    __syncthreads();

    int k = blk * 256 + tid;
    if (k < Kp) {
        if (k < K) {
            float acc[10];
            #pragma unroll
            for (int j = 0; j < 10; j++) acc[j] = 0.f;
            #pragma unroll 4
            for (int r = 0; r < 500; r++) {
                float a = __ldg(&l1[(size_t)r * K + k]);
                float4 w0 = *(const float4*)&l2T[r * 12];
                float4 w1 = *(const float4*)&l2T[r * 12 + 4];
                float2 w2 = *(const float2*)&l2T[r * 12 + 8];
                acc[0] += a * w0.x; acc[1] += a * w0.y; acc[2] += a * w0.z; acc[3] += a * w0.w;
                acc[4] += a * w1.x; acc[5] += a * w1.y; acc[6] += a * w1.z; acc[7] += a * w1.w;
                acc[8] += a * w2.x; acc[9] += a * w2.y;
            }
            #pragma unroll
            for (int j = 0; j < 10; j++) W12[(size_t)j * Kp + k] = acc[j];
            W12[(size_t)10 * Kp + k] = __ldg(&dw[k]);
            W12[(size_t)11 * Kp + k] = __ldg(&dw[K + k]);
        } else {
            #pragma unroll
            for (int j = 0; j < 12; j++) W12[(size_t)j * Kp + k] = 0.f;
        }
    }
    if (blk == 0) {
        if (tid < 10) {
            float a = b2[tid];
            for (int r = 0; r < 500; r++) a += l2[tid * 500 + r] * b1[r];
            bc12[tid] = a;
        } else if (tid < 12) {
            bc12[tid] = db[tid - 10];
        }
    }
}

__global__ __launch_bounds__(256) void prep_kernel(
    const float* l1c1_w, const float* l1c1_b, const float* l2c1_w, const float* l2c1_b,
    const float* l1c2_w, const float* l1c2_b, const float* l2c2_w, const float* l2c2_b,
    const float* d1_w, const float* d1_b, const float* d2_w, const float* d2_b,
    const float* c2_w,
    float* W1, float* b1c, float* W2, float* b2c, float2* wpk2)
{
    __shared__ __align__(16) float l2T[500 * 12];
    int bx = blockIdx.x, tid = threadIdx.x;
    if (bx < 34) {
        combine_part(l1c1_w, l1c1_b, l2c1_w, l2c1_b, d1_w, d1_b, K1, KP1P, W1, b1c, bx, l2T);
    } else if (bx < 40) {
        combine_part(l1c2_w, l1c2_b, l2c2_w, l2c2_b, d2_w, d2_b, K2, KP2P, W2, b2c, bx - 34, l2T);
    } else {
        int i = (bx - 40) * 256 + tid;
        if (i < 22500) {
            int oc = i / 450, r = i - oc * 450;
            int ic = r / 9, k = r - ic * 9;
            float v = c2_w[i];
            wpk2[ic * 500 + oc * 10 + k] = make_float2(v, v);   // pad k=9 stays zero
        }
    }
}

// ---------------- conv1: register patch + packed f32x2 ----------------------
__global__ __launch_bounds__(192) void conv1_kernel(
    const float* __restrict__ x, const float* __restrict__ w,
    const float* __restrict__ bias, float* __restrict__ h1, int bbase)
{
    int b = bbase + blockIdx.x;
    __shared__ __align__(16) float xs[784];
    __shared__ __align__(16) float2 ws[450];
    __shared__ __align__(16) float bs[50];
    int tid = threadIdx.x;
    {
        const float4* xb = (const float4*)(x + (size_t)b * 784);
        for (int i = tid; i < 196; i += 192) ((float4*)xs)[i] = xb[i];
        for (int i = tid; i < 450; i += 192) { float v = w[i]; ws[i] = make_float2(v, v); }
        for (int i = tid; i < 50;  i += 192) bs[i] = bias[i];
    }
    __syncthreads();
    if (tid >= 169) return;

    const int py = tid / 13, px = tid % 13;
    const int Y = 2 * py, X = 2 * px;
    float p[4][4];
    #pragma unroll
    for (int r = 0; r < 4; r++)
        #pragma unroll
        for (int c = 0; c < 4; c++) p[r][c] = xs[(Y + r) * 28 + X + c];
    unsigned long long P[4][3];
    #pragma unroll
    for (int r = 0; r < 4; r++)
        #pragma unroll
        for (int k = 0; k < 3; k++)
            asm("mov.b64 %0, {%1, %2};" : "=l"(P[r][k])
                : "r"(__float_as_uint(p[r][k])), "r"(__float_as_uint(p[r][k + 1])));

    float* hb = h1 + (size_t)b * KP1P + tid;
    for (int oc = 0; oc < 50; oc++) {
        unsigned long long aT = 0ULL, aB = 0ULL;
        #pragma unroll
        for (int ky = 0; ky < 3; ky++)
            #pragma unroll
            for (int kx = 0; kx < 3; kx++) {
                unsigned long long w2 = *(const unsigned long long*)&ws[oc * 9 + ky * 3 + kx];
                asm("fma.rn.f32x2 %0, %1, %2, %0;" : "+l"(aT) : "l"(P[ky][kx]), "l"(w2));
                asm("fma.rn.f32x2 %0, %1, %2, %0;" : "+l"(aB) : "l"(P[ky + 1][kx]), "l"(w2));
            }
        unsigned int u0, u1, u2, u3;
        asm("mov.b64 {%0, %1}, %2;" : "=r"(u0), "=r"(u1) : "l"(aT));
        asm("mov.b64 {%0, %1}, %2;" : "=r"(u2), "=r"(u3) : "l"(aB));
        float m = fmaxf(fmaxf(__uint_as_float(u0), __uint_as_float(u1)),
                        fmaxf(__uint_as_float(u2), __uint_as_float(u3)));
        m += bs[oc];
        hb[oc * 169] = fmaxf(m, 0.f);
    }
}

// ====== stagehead v3: smem weights (double-buffered) + register features ====
// block = 16 samples (8 warps x 2), K chunked by 512, grid (HALF/16, 2 splits)
#define SH_SMEM (2 * 12 * 512 * 4)     // 48 KB
__global__ __launch_bounds__(256, 3) void stagehead_part_kernel(
    const float* __restrict__ f, int Kp,
    const float* __restrict__ W12, float* __restrict__ part, int bbase)
{
    extern __shared__ __align__(16) float ws[];   // [2][12][512]
    const int tid = threadIdx.x, lane = tid & 31, wid = tid >> 5;
    const int b0 = bbase + blockIdx.x * 16;
    const int split = blockIdx.y;
    const int s0 = b0 + wid * 2, s1 = s0 + 1;
    const int cBeg = split ? 9 : 0;
    const int cEnd = split ? 17 : 9;

    float acc0[12], acc1[12];
    #pragma unroll
    for (int j = 0; j < 12; j++) { acc0[j] = 0.f; acc1[j] = 0.f; }

    const float* f0p = f + (size_t)s0 * Kp;
    const float* f1p = f + (size_t)s1 * Kp;

    // stage first weight chunk
    {
        const int c = cBeg;
        for (int i = tid; i < 1536; i += 256) {
            int j = i >> 7, k4 = (i & 127) * 4;
            *(float4*)&ws[j * 512 + k4] =
                *(const float4*)&W12[(size_t)j * Kp + c * 512 + k4];
        }
    }
    __syncthreads();

    for (int c = cBeg; c < cEnd; c++) {
        const int buf = (c - cBeg) & 1;
        // prefetch next weight chunk into the other buffer
        if (c + 1 < cEnd) {
            const int nb = buf ^ 1;
            for (int i = tid; i < 1536; i += 256) {
                int j = i >> 7, k4 = (i & 127) * 4;
                *(float4*)&ws[nb * 6144 + j * 512 + k4] =
                    *(const float4*)&W12[(size_t)j * Kp + (c + 1) * 512 + k4];
            }
        }
        // prefetch all features of this chunk (8 independent LDG.128)
        const int kc = c * 512;
        float4 A0[4], A1[4];
        #pragma unroll
        for (int it = 0; it < 4; it++) {
            A0[it] = *(const float4*)(f0p + kc + it * 128 + lane * 4);
            A1[it] = *(const float4*)(f1p + kc + it * 128 + lane * 4);
        }
        const float* wb = ws + buf * 6144;
        #pragma unroll
        for (int it = 0; it < 4; it++) {
            const int kk = it * 128 + lane * 4;
            float4 a0 = A0[it], a1 = A1[it];
            #pragma unroll
            for (int j = 0; j < 12; j++) {
                float4 w = *(const float4*)&wb[j * 512 + kk];
                acc0[j] = fmaf(a0.x, w.x, fmaf(a0.y, w.y, fmaf(a0.z, w.z, fmaf(a0.w, w.w, acc0[j]))));
                acc1[j] = fmaf(a1.x, w.x, fmaf(a1.y, w.y, fmaf(a1.z, w.z, fmaf(a1.w, w.w, acc1[j]))));
            }
        }
        __syncthreads();
    }

    #pragma unroll
    for (int j = 0; j < 12; j++) {
        #pragma unroll
        for (int off = 16; off; off >>= 1) {
            acc0[j] += __shfl_xor_sync(0xffffffffu, acc0[j], off);
            acc1[j] += __shfl_xor_sync(0xffffffffu, acc1[j], off);
        }
    }
    if (lane == 0) {
        #pragma unroll
        for (int j = 0; j < 12; j++) {
            part[s0 * 24 + split * 12 + j] = acc0[j];
            part[s1 * 24 + split * 12 + j] = acc1[j];
        }
    }
}

// ====== conv2 mega: conv2 + stage-2 head + conv3, double-buffered weights ===
#define C2_SMEM 86064
__global__ __launch_bounds__(256, 2) void conv2_kernel(
    const float* __restrict__ h1, const float2* __restrict__ wpk,
    const float* __restrict__ bias, const float* __restrict__ part,
    const float* __restrict__ b1c,
    const float* __restrict__ W2, const float* __restrict__ b2c,
    const float* __restrict__ c3_w, const float* __restrict__ c3_b,
    int* __restrict__ e1, int* __restrict__ e2,
    float* __restrict__ o2, float* __restrict__ f3, int bbase)
{
    extern __shared__ __align__(16) char csm[];
    float*  hs   = (float*)csm;
    float2* wb   = (float2*)(csm + 36416);
    float*  h2s  = (float*)(csm + 76416);
    float*  bss  = (float*)(csm + 81416);
    float*  red  = (float*)(csm + 81616);
    float*  red3 = (float*)(csm + 82064);
    __shared__ int sflag;

    const int b = bbase + blockIdx.x;
    const int tid = threadIdx.x;
    if (tid == 0) {
        float m0 = part[b * 24 + 10] + part[b * 24 + 22] + __ldg(&b1c[10]);
        float m1 = part[b * 24 + 11] + part[b * 24 + 23] + __ldg(&b1c[11]);
        int fl = (m0 >= m1) ? 1 : 0;
        e1[b] = fl;
        sflag = fl;
        if (fl) e2[b] = 0;     // deterministic; unused when e1 selected
    }
    __syncthreads();
    if (sflag) return;

    {
        const float* hb = h1 + (size_t)b * KP1P;
        for (int i = tid; i < 8450; i += 256) {
            int ic = i / 169, rem = i - ic * 169;
            int r = rem / 13, c = rem - r * 13;
            hs[ic * 182 + r * 14 + c] = hb[i];
        }
        for (int i = tid; i < 50; i += 256) bss[i] = bias[i];
        for (int i = tid; i < 1250; i += 256)
            ((float4*)wb)[i] = ((const float4*)wpk)[i];
    }
    __syncthreads();

    const int osub = tid / 25, pos = tid % 25;
    const int oc0 = osub * 5;
    const int py = pos / 5, px = pos % 5;
    const int Y = 2 * py, X = 2 * px;
    const bool active = (tid < 250);

    unsigned long long aT[5], aB[5];
    #pragma unroll
    for (int j = 0; j < 5; j++) { aT[j] = 0ULL; aB[j] = 0ULL; }

    for (int t = 0; t < 10; t++) {
        const int cur = t & 1;
        if (t + 1 < 10) {
            const float4* src = (const float4*)wpk + (t + 1) * 1250;
            float4* dst = (float4*)(wb + (cur ^ 1) * 2500);
            for (int i = tid; i < 1250; i += 256) dst[i] = src[i];
        }
        if (active) {
            #pragma unroll
            for (int i5 = 0; i5 < 5; i5++) {
                const float* hc = hs + (t * 5 + i5) * 182;
                unsigned long long P[4][3];
                #pragma unroll
                for (int r = 0; r < 4; r++) {
                    float2 v0 = *(const float2*)(hc + (Y + r) * 14 + X);
                    float2 v1 = *(const float2*)(hc + (Y + r) * 14 + X + 2);
                    asm("mov.b64 %0, {%1, %2};" : "=l"(P[r][0])
                        : "r"(__float_as_uint(v0.x)), "r"(__float_as_uint(v0.y)));
                    asm("mov.b64 %0, {%1, %2};" : "=l"(P[r][1])
                        : "r"(__float_as_uint(v0.y)), "r"(__float_as_uint(v1.x)));
                    asm("mov.b64 %0, {%1, %2};" : "=l"(P[r][2])
                        : "r"(__float_as_uint(v1.x)), "r"(__float_as_uint(v1.y)));
                }
                const float2* wrow = wb + cur * 2500 + (i5 * 50 + oc0) * 10;
                #pragma unroll
                for (int j = 0; j < 5; j++) {
                    const float2* wp = wrow + j * 10;
                    ulonglong2 q0 = *(const ulonglong2*)(wp);
                    ulonglong2 q1 = *(const ulonglong2*)(wp + 2);
                    ulonglong2 q2 = *(const ulonglong2*)(wp + 4);
                    ulonglong2 q3 = *(const ulonglong2*)(wp + 6);
                    unsigned long long w8 = *(const unsigned long long*)(wp + 8);
                    unsigned long long wv[9] = {q0.x, q0.y, q1.x, q1.y,
                                                q2.x, q2.y, q3.x, q3.y, w8};
                    #pragma unroll
                    for (int ky = 0; ky < 3; ky++)
                        #pragma unroll
                        for (int kx = 0; kx < 3; kx++) {
                            asm("fma.rn.f32x2 %0, %1, %2, %0;"
                                : "+l"(aT[j]) : "l"(P[ky][kx]), "l"(wv[ky * 3 + kx]));
                            asm("fma.rn.f32x2 %0, %1, %2, %0;"
                                : "+l"(aB[j]) : "l"(P[ky + 1][kx]), "l"(wv[ky * 3 + kx]));
                        }
                }
            }
        }
        __syncthreads();
    }

    float hd[12];
    #pragma unroll
    for (int jj = 0; jj < 12; jj++) hd[jj] = 0.f;
    if (active) {
        float v5[5];
        #pragma unroll
        for (int j = 0; j < 5; j++) {
            unsigned int u0, u1, u2, u3;
            asm("mov.b64 {%0, %1}, %2;" : "=r"(u0), "=r"(u1) : "l"(aT[j]));
            asm("mov.b64 {%0, %1}, %2;" : "=r"(u2), "=r"(u3) : "l"(aB[j]));
            float m = fmaxf(fmaxf(__uint_as_float(u0), __uint_as_float(u1)),
                            fmaxf(__uint_as_float(u2), __uint_as_float(u3)));
            m += bss[oc0 + j];
            v5[j] = fmaxf(m, 0.f);
            h2s[(oc0 + j) * 25 + pos] = v5[j];
        }
        #pragma unroll
        for (int jj = 0; jj < 12; jj++) {
            float s = 0.f;
            #pragma unroll
            for (int j = 0; j < 5; j++)
                s += v5[j] * __ldg(&W2[(size_t)jj * KP2P + (oc0 + j) * 25 + pos]);
            hd[jj] = s;
        }
    }
    const int lane = tid & 31, wrp = tid >> 5;
    #pragma unroll
    for (int jj = 0; jj < 12; jj++) {
        #pragma unroll
        for (int off = 16; off; off >>= 1)
            hd[jj] += __shfl_xor_sync(0xffffffffu, hd[jj], off);
    }
    if (lane == 0) {
        #pragma unroll
        for (int jj = 0; jj < 12; jj++) red[jj * 8 + wrp] = hd[jj];
    }
    __syncthreads();
    if (tid < 12) {
        float s = __ldg(&b2c[tid]);
        #pragma unroll
        for (int w = 0; w < 8; w++) s += red[tid * 8 + w];
        red[96 + tid] = s;
    }
    __syncthreads();

    const float em0 = red[96 + 10], em1 = red[96 + 11];
    if (tid == 0) e2[b] = (em0 >= em1) ? 1 : 0;
    if (tid < 10) o2[b * 10 + tid] = red[96 + tid];
    if (em0 >= em1) return;

    // ---- fused conv3: h2s (smem) -> f3 ----
    if (tid < 250) {
        const int oc2 = tid % 50, grp = tid / 50;
        const float* w3 = c3_w + oc2 * 450 + grp * 90;
        float a0 = 0.f, a1 = 0.f, a2 = 0.f, a3 = 0.f;
        #pragma unroll
        for (int i2 = 0; i2 < 10; i2++) {
            const float* hc = h2s + (grp * 10 + i2) * 25;
            #pragma unroll
            for (int ky = 0; ky < 3; ky++)
                #pragma unroll
                for (int kx = 0; kx < 3; kx++) {
                    float wv = __ldg(&w3[i2 * 9 + ky * 3 + kx]);
                    a0 += hc[ky * 5 + kx] * wv;
                    a1 += hc[ky * 5 + kx + 1] * wv;
                    a2 += hc[(ky + 1) * 5 + kx] * wv;
                    a3 += hc[(ky + 1) * 5 + kx + 1] * wv;
                }
        }
        float* r3 = red3 + grp * 200 + oc2 * 4;
        r3[0] = a0; r3[1] = a1; r3[2] = a2; r3[3] = a3;
    }
    __syncthreads();
    if (tid < 50) {
        float a0 = 0.f, a1 = 0.f, a2 = 0.f, a3 = 0.f;
        #pragma unroll
        for (int g = 0; g < 5; g++) {
            const float* r3 = red3 + g * 200 + tid * 4;
            a0 += r3[0]; a1 += r3[1]; a2 += r3[2]; a3 += r3[3];
        }
        float m = fmaxf(fmaxf(a0, a1), fmaxf(a2, a3)) + __ldg(&c3_b[tid]);
        f3[b * 50 + tid] = fmaxf(m, 0.f);
    }
}

// ==== stage3 + final fused ===================================================
#define S3_G 32
#define S3_SMEM ((25000 + 5000 + 500 + S3_G * 50 + S3_G * 500 + S3_G * 10) * 4)

__global__ __launch_bounds__(256) void stage3final_kernel(
    const float* __restrict__ f3,
    const float* __restrict__ l1w, const float* __restrict__ l1b,
    const float* __restrict__ l2w, const float* __restrict__ l2b,
    const int* __restrict__ e1, const int* __restrict__ e2,
    const float* __restrict__ part, const float* __restrict__ b1c,
    const float* __restrict__ o2, float* __restrict__ out, int bbase)
{
    extern __shared__ __align__(16) float sm[];
    float* w1  = sm;
    float* w2  = sm + 25000;
    float* b1  = sm + 30000;
    float* fs  = sm + 30500;
    float* hid = sm + 32100;
    float* o3s = sm + 48100;
    int tid = threadIdx.x;
    int b0 = bbase + blockIdx.x * S3_G;

    for (int i = tid; i < 25000; i += 256) w1[i] = l1w[i];
    for (int i = tid; i < 5000;  i += 256) w2[i] = l2w[i];
    for (int i = tid; i < 500;   i += 256) b1[i] = l1b[i];
    for (int i = tid; i < S3_G * 50; i += 256) fs[i] = f3[b0 * 50 + i];
    __syncthreads();

    for (int hh = tid; hh < S3_G * 500; hh += 256) {
        int s = hh / 500, j = hh - s * 500;
        float a = b1[j];
        const float* fr = fs + s * 50;
        const float* wr = w1 + j * 50;
        #pragma unroll 10
        for (int k = 0; k < 50; k++) a += fr[k] * wr[k];
        hid[hh] = fmaxf(a, 0.f);
    }
    __syncthreads();

    for (int oo = tid; oo < S3_G * 10; oo += 256) {
        int s = oo / 10, n = oo - s * 10;
        float a = __ldg(&l2b[n]);
        const float* hr = hid + s * 500;
        const float* wr = w2 + n * 500;
        #pragma unroll 4
        for (int j = 0; j < 500; j++) a += hr[j] * wr[j];
        o3s[s * 10 + n] = a;
    }
    __syncthreads();

    if (tid < S3_G) {
        int b = b0 + tid;
        float v[10];
        if (e1[b]) {
            #pragma unroll
            for (int j = 0; j < 10; j++)
                v[j] = part[b * 24 + j] + part[b * 24 + 12 + j] + __ldg(&b1c[j]);
        } else if (e2[b]) {
            #pragma unroll
            for (int j = 0; j < 10; j++) v[j] = o2[b * 10 + j];
        } else {
            #pragma unroll
            for (int j = 0; j < 10; j++) v[j] = o3s[tid * 10 + j];
        }
        float mx = -1e30f;
        #pragma unroll
        for (int j = 0; j < 10; j++) mx = fmaxf(mx, v[j]);
        float sum = 0.f;
        #pragma unroll
        for (int j = 0; j < 10; j++) sum += expf(v[j] - mx);
        float l = logf(sum);
        #pragma unroll
        for (int j = 0; j < 10; j++) out[b * 10 + j] = v[j] - mx - l;
    }
}

// ---------------- launch ----------------------------------------------------
extern "C" void kernel_launch(void* const* d_in, const int* in_sizes, int n_in,
                              void* d_out, int out_size)
{
    const float* x      = (const float*)d_in[0];
    const float* c1_w   = (const float*)d_in[1];
    const float* c1_b   = (const float*)d_in[2];
    const float* c2_w   = (const float*)d_in[3];
    const float* c2_b   = (const float*)d_in[4];
    const float* c3_w   = (const float*)d_in[5];
    const float* c3_b   = (const float*)d_in[6];
    const float* l1c1_w = (const float*)d_in[7];
    const float* l1c1_b = (const float*)d_in[8];
    const float* l2c1_w = (const float*)d_in[9];
    const float* l2c1_b = (const float*)d_in[10];
    const float* l1c2_w = (const float*)d_in[11];
    const float* l1c2_b = (const float*)d_in[12];
    const float* l2c2_w = (const float*)d_in[13];
    const float* l2c2_b = (const float*)d_in[14];
    const float* l1_w   = (const float*)d_in[15];
    const float* l1_b   = (const float*)d_in[16];
    const float* l2_w   = (const float*)d_in[17];
    const float* l2_b   = (const float*)d_in[18];
    const float* d1_w   = (const float*)d_in[19];
    const float* d1_b   = (const float*)d_in[20];
    const float* d2_w   = (const float*)d_in[21];
    const float* d2_b   = (const float*)d_in[22];
    float* out = (float*)d_out;

    float *h1, *f3, *o2, *W1, *W2, *b1c, *b2c, *part1;
    float2 *wpk2;
    int *e1, *e2;
    cudaGetSymbolAddress((void**)&h1,   g_h1);
    cudaGetSymbolAddress((void**)&f3,   g_f3);
    cudaGetSymbolAddress((void**)&o2,   g_o2);
    cudaGetSymbolAddress((void**)&e1,   g_e1);
    cudaGetSymbolAddress((void**)&e2,   g_e2);
    cudaGetSymbolAddress((void**)&W1,   g_W1);
    cudaGetSymbolAddress((void**)&W2,   g_W2);
    cudaGetSymbolAddress((void**)&b1c,  g_b1c);
    cudaGetSymbolAddress((void**)&b2c,  g_b2c);
    cudaGetSymbolAddress((void**)&part1, g_part1);
    cudaGetSymbolAddress((void**)&wpk2, g_wpk2);

    static cudaStream_t s2 = nullptr, s3 = nullptr;
    static cudaEvent_t evA = nullptr, evP = nullptr, evC = nullptr;
    static int attr_set = 0;
    if (!attr_set) {
        cudaFuncSetAttribute(stagehead_part_kernel,
                             cudaFuncAttributeMaxDynamicSharedMemorySize, SH_SMEM);
        cudaFuncSetAttribute(conv2_kernel,
                             cudaFuncAttributeMaxDynamicSharedMemorySize, C2_SMEM);
        cudaFuncSetAttribute(stage3final_kernel,
                             cudaFuncAttributeMaxDynamicSharedMemorySize, S3_SMEM);
        cudaStreamCreateWithFlags(&s2, cudaStreamNonBlocking);
        cudaStreamCreateWithFlags(&s3, cudaStreamNonBlocking);
        cudaEventCreateWithFlags(&evA, cudaEventDisableTiming);
        cudaEventCreateWithFlags(&evP, cudaEventDisableTiming);
        cudaEventCreateWithFlags(&evC, cudaEventDisableTiming);
        attr_set = 1;
    }

    // fork both side streams from main
    cudaEventRecord(evA, 0);
    cudaStreamWaitEvent(s2, evA, 0);
    cudaStreamWaitEvent(s3, evA, 0);

    // prep on s2
    prep_kernel<<<128, 256, 0, s2>>>(l1c1_w, l1c1_b, l2c1_w, l2c1_b,
                                     l1c2_w, l1c2_b, l2c2_w, l2c2_b,
                                     d1_w, d1_b, d2_w, d2_b, c2_w,
                                     W1, b1c, W2, b2c, wpk2);
    cudaEventRecord(evP, s2);

    // chain 0 on main (half 0), chain 1 on s3 (half 1)
    conv1_kernel<<<HALF, 192>>>(x, c1_w, c1_b, h1, 0);
    conv1_kernel<<<HALF, 192, 0, s3>>>(x, c1_w, c1_b, h1, HALF);

    cudaStreamWaitEvent(0, evP, 0);
    cudaStreamWaitEvent(s3, evP, 0);

    stagehead_part_kernel<<<dim3(HALF / 16, 2), 256, SH_SMEM>>>(h1, KP1P, W1, part1, 0);
    stagehead_part_kernel<<<dim3(HALF / 16, 2), 256, SH_SMEM, s3>>>(h1, KP1P, W1, part1, HALF);

    conv2_kernel<<<HALF, 256, C2_SMEM>>>(h1, wpk2, c2_b, part1, b1c,
                                         W2, b2c, c3_w, c3_b, e1, e2, o2, f3, 0);
    conv2_kernel<<<HALF, 256, C2_SMEM, s3>>>(h1, wpk2, c2_b, part1, b1c,
                                             W2, b2c, c3_w, c3_b, e1, e2, o2, f3, HALF);

    stage3final_kernel<<<HALF / S3_G, 256, S3_SMEM>>>(
        f3, l1_w, l1_b, l2_w, l2_b, e1, e2, part1, b1c, o2, out, 0);
    stage3final_kernel<<<HALF / S3_G, 256, S3_SMEM, s3>>>(
        f3, l1_w, l1_b, l2_w, l2_b, e1, e2, part1, b1c, o2, out, HALF);

    // join chain 1 back into main
    cudaEventRecord(evC, s3);
    cudaStreamWaitEvent(0, evC, 0);
}

// round 16
// speedup vs baseline: 1.1205x; 1.0223x over previous
#include <cuda_runtime.h>
#include <math.h>
#include <stdint.h>

#define BATCH 4096
#define HALF 2048
#define K1 8450
#define K2 1250
#define KP1P 8704          // h1 row pitch (17 * 512)
#define KP2P 1536          // W2 row pitch

// ---------------- scratch (device globals; zero-initialized) ---------------
__device__ float g_h1[(size_t)BATCH * KP1P];
__device__ float g_f3[BATCH * 50];
__device__ float g_o2[BATCH * 10];
__device__ int   g_e1[BATCH];
__device__ int   g_e2[BATCH];
__device__ float g_W1[12 * KP1P];    // rows 0-9: l2c1@l1c1; 10-11: d1_w
__device__ float g_W2[12 * KP2P];
__device__ float g_b1c[12];
__device__ float g_b2c[12];
__device__ float g_part1[BATCH * 48];  // [b][split(4)][12]
__device__ float2 g_wpk2[50 * 500];    // conv2 weights [ic][oc][10] dup, pad k=9 zero

// ================= merged prep kernel =======================================
__device__ void combine_part(
    const float* __restrict__ l1, const float* __restrict__ b1,
    const float* __restrict__ l2, const float* __restrict__ b2,
    const float* __restrict__ dw, const float* __restrict__ db,
    int K, int Kp, float* __restrict__ W12, float* __restrict__ bc12,
    int blk, float* l2T)
{
    int tid = threadIdx.x;
    for (int i = tid; i < 5000; i += 256) {
        int j = i / 500, r = i - j * 500;
        l2T[r * 12 + j] = l2[i];
    }
    for (int r = tid; r < 500; r += 256) { l2T[r * 12 + 10] = 0.f; l2T[r * 12 + 11] = 0.f; }
    __syncthreads();

    int k = blk * 256 + tid;
    if (k < Kp) {
        if (k < K) {
            float acc[10];
            #pragma unroll
            for (int j = 0; j < 10; j++) acc[j] = 0.f;
            #pragma unroll 4
            for (int r = 0; r < 500; r++) {
                float a = __ldg(&l1[(size_t)r * K + k]);
                float4 w0 = *(const float4*)&l2T[r * 12];
                float4 w1 = *(const float4*)&l2T[r * 12 + 4];
                float2 w2 = *(const float2*)&l2T[r * 12 + 8];
                acc[0] += a * w0.x; acc[1] += a * w0.y; acc[2] += a * w0.z; acc[3] += a * w0.w;
                acc[4] += a * w1.x; acc[5] += a * w1.y; acc[6] += a * w1.z; acc[7] += a * w1.w;
                acc[8] += a * w2.x; acc[9] += a * w2.y;
            }
            #pragma unroll
            for (int j = 0; j < 10; j++) W12[(size_t)j * Kp + k] = acc[j];
            W12[(size_t)10 * Kp + k] = __ldg(&dw[k]);
            W12[(size_t)11 * Kp + k] = __ldg(&dw[K + k]);
        } else {
            #pragma unroll
            for (int j = 0; j < 12; j++) W12[(size_t)j * Kp + k] = 0.f;
        }
    }
    if (blk == 0) {
        if (tid < 10) {
            float a = b2[tid];
            for (int r = 0; r < 500; r++) a += l2[tid * 500 + r] * b1[r];
            bc12[tid] = a;
        } else if (tid < 12) {
            bc12[tid] = db[tid - 10];
        }
    }
}

__global__ __launch_bounds__(256) void prep_kernel(
    const float* l1c1_w, const float* l1c1_b, const float* l2c1_w, const float* l2c1_b,
    const float* l1c2_w, const float* l1c2_b, const float* l2c2_w, const float* l2c2_b,
    const float* d1_w, const float* d1_b, const float* d2_w, const float* d2_b,
    const float* c2_w,
    float* W1, float* b1c, float* W2, float* b2c, float2* wpk2)
{
    __shared__ __align__(16) float l2T[500 * 12];
    int bx = blockIdx.x, tid = threadIdx.x;
    if (bx < 34) {
        combine_part(l1c1_w, l1c1_b, l2c1_w, l2c1_b, d1_w, d1_b, K1, KP1P, W1, b1c, bx, l2T);
    } else if (bx < 40) {
        combine_part(l1c2_w, l1c2_b, l2c2_w, l2c2_b, d2_w, d2_b, K2, KP2P, W2, b2c, bx - 34, l2T);
    } else {
        int i = (bx - 40) * 256 + tid;
        if (i < 22500) {
            int oc = i / 450, r = i - oc * 450;
            int ic = r / 9, k = r - ic * 9;
            float v = c2_w[i];
            wpk2[ic * 500 + oc * 10 + k] = make_float2(v, v);   // pad k=9 stays zero
        }
    }
}

// ---------------- conv1: register patch + packed f32x2 ----------------------
__global__ __launch_bounds__(192) void conv1_kernel(
    const float* __restrict__ x, const float* __restrict__ w,
    const float* __restrict__ bias, float* __restrict__ h1, int bbase)
{
    int b = bbase + blockIdx.x;
    __shared__ __align__(16) float xs[784];
    __shared__ __align__(16) float2 ws[450];
    __shared__ __align__(16) float bs[50];
    int tid = threadIdx.x;
    {
        const float4* xb = (const float4*)(x + (size_t)b * 784);
        for (int i = tid; i < 196; i += 192) ((float4*)xs)[i] = xb[i];
        for (int i = tid; i < 450; i += 192) { float v = w[i]; ws[i] = make_float2(v, v); }
        for (int i = tid; i < 50;  i += 192) bs[i] = bias[i];
    }
    __syncthreads();
    if (tid >= 169) return;

    const int py = tid / 13, px = tid % 13;
    const int Y = 2 * py, X = 2 * px;
    float p[4][4];
    #pragma unroll
    for (int r = 0; r < 4; r++)
        #pragma unroll
        for (int c = 0; c < 4; c++) p[r][c] = xs[(Y + r) * 28 + X + c];
    unsigned long long P[4][3];
    #pragma unroll
    for (int r = 0; r < 4; r++)
        #pragma unroll
        for (int k = 0; k < 3; k++)
            asm("mov.b64 %0, {%1, %2};" : "=l"(P[r][k])
                : "r"(__float_as_uint(p[r][k])), "r"(__float_as_uint(p[r][k + 1])));

    float* hb = h1 + (size_t)b * KP1P + tid;
    for (int oc = 0; oc < 50; oc++) {
        unsigned long long aT = 0ULL, aB = 0ULL;
        #pragma unroll
        for (int ky = 0; ky < 3; ky++)
            #pragma unroll
            for (int kx = 0; kx < 3; kx++) {
                unsigned long long w2 = *(const unsigned long long*)&ws[oc * 9 + ky * 3 + kx];
                asm("fma.rn.f32x2 %0, %1, %2, %0;" : "+l"(aT) : "l"(P[ky][kx]), "l"(w2));
                asm("fma.rn.f32x2 %0, %1, %2, %0;" : "+l"(aB) : "l"(P[ky + 1][kx]), "l"(w2));
            }
        unsigned int u0, u1, u2, u3;
        asm("mov.b64 {%0, %1}, %2;" : "=r"(u0), "=r"(u1) : "l"(aT));
        asm("mov.b64 {%0, %1}, %2;" : "=r"(u2), "=r"(u3) : "l"(aB));
        float m = fmaxf(fmaxf(__uint_as_float(u0), __uint_as_float(u1)),
                        fmaxf(__uint_as_float(u2), __uint_as_float(u3)));
        m += bs[oc];
        hb[oc * 169] = fmaxf(m, 0.f);
    }
}

// ====== stagehead v4: smem weights double-buffered, 4 K-splits ==============
// block = 16 samples (8 warps x 2); grid (HALF/16, 4)
// split 0: chunks 0-4; splits 1-3: 4 chunks each (17 total chunks of 512)
#define SH_SMEM (2 * 12 * 512 * 4)     // 48 KB
__global__ __launch_bounds__(256, 3) void stagehead_part_kernel(
    const float* __restrict__ f, int Kp,
    const float* __restrict__ W12, float* __restrict__ part, int bbase)
{
    extern __shared__ __align__(16) float ws[];   // [2][12][512]
    const int tid = threadIdx.x, lane = tid & 31, wid = tid >> 5;
    const int b0 = bbase + blockIdx.x * 16;
    const int split = blockIdx.y;
    const int s0 = b0 + wid * 2, s1 = s0 + 1;
    const int cBeg = split ? (4 * split + 1) : 0;
    const int cEnd = 4 * split + 5;

    float acc0[12], acc1[12];
    #pragma unroll
    for (int j = 0; j < 12; j++) { acc0[j] = 0.f; acc1[j] = 0.f; }

    const float* f0p = f + (size_t)s0 * Kp;
    const float* f1p = f + (size_t)s1 * Kp;

    // stage first weight chunk
    {
        const int c = cBeg;
        for (int i = tid; i < 1536; i += 256) {
            int j = i >> 7, k4 = (i & 127) * 4;
            *(float4*)&ws[j * 512 + k4] =
                *(const float4*)&W12[(size_t)j * Kp + c * 512 + k4];
        }
    }
    __syncthreads();

    for (int c = cBeg; c < cEnd; c++) {
        const int buf = (c - cBeg) & 1;
        if (c + 1 < cEnd) {
            const int nb = buf ^ 1;
            for (int i = tid; i < 1536; i += 256) {
                int j = i >> 7, k4 = (i & 127) * 4;
                *(float4*)&ws[nb * 6144 + j * 512 + k4] =
                    *(const float4*)&W12[(size_t)j * Kp + (c + 1) * 512 + k4];
            }
        }
        const int kc = c * 512;
        float4 A0[4], A1[4];
        #pragma unroll
        for (int it = 0; it < 4; it++) {
            A0[it] = *(const float4*)(f0p + kc + it * 128 + lane * 4);
            A1[it] = *(const float4*)(f1p + kc + it * 128 + lane * 4);
        }
        const float* wb = ws + buf * 6144;
        #pragma unroll
        for (int it = 0; it < 4; it++) {
            const int kk = it * 128 + lane * 4;
            float4 a0 = A0[it], a1 = A1[it];
            #pragma unroll
            for (int j = 0; j < 12; j++) {
                float4 w = *(const float4*)&wb[j * 512 + kk];
                acc0[j] = fmaf(a0.x, w.x, fmaf(a0.y, w.y, fmaf(a0.z, w.z, fmaf(a0.w, w.w, acc0[j]))));
                acc1[j] = fmaf(a1.x, w.x, fmaf(a1.y, w.y, fmaf(a1.z, w.z, fmaf(a1.w, w.w, acc1[j]))));
            }
        }
        __syncthreads();
    }

    #pragma unroll
    for (int j = 0; j < 12; j++) {
        #pragma unroll
        for (int off = 16; off; off >>= 1) {
            acc0[j] += __shfl_xor_sync(0xffffffffu, acc0[j], off);
            acc1[j] += __shfl_xor_sync(0xffffffffu, acc1[j], off);
        }
    }
    if (lane == 0) {
        #pragma unroll
        for (int j = 0; j < 12; j++) {
            part[s0 * 48 + split * 12 + j] = acc0[j];
            part[s1 * 48 + split * 12 + j] = acc1[j];
        }
    }
}

// ====== conv2 mega: conv2 + stage-2 head + conv3, double-buffered weights ===
#define C2_SMEM 86064
__global__ __launch_bounds__(256, 2) void conv2_kernel(
    const float* __restrict__ h1, const float2* __restrict__ wpk,
    const float* __restrict__ bias, const float* __restrict__ part,
    const float* __restrict__ b1c,
    const float* __restrict__ W2, const float* __restrict__ b2c,
    const float* __restrict__ c3_w, const float* __restrict__ c3_b,
    int* __restrict__ e1, int* __restrict__ e2,
    float* __restrict__ o2, float* __restrict__ f3, int bbase)
{
    extern __shared__ __align__(16) char csm[];
    float*  hs   = (float*)csm;
    float2* wb   = (float2*)(csm + 36416);
    float*  h2s  = (float*)(csm + 76416);
    float*  bss  = (float*)(csm + 81416);
    float*  red  = (float*)(csm + 81616);
    float*  red3 = (float*)(csm + 82064);
    __shared__ int sflag;

    const int b = bbase + blockIdx.x;
    const int tid = threadIdx.x;
    if (tid == 0) {
        float m0 = (part[b * 48 + 10] + part[b * 48 + 22])
                 + (part[b * 48 + 34] + part[b * 48 + 46]) + __ldg(&b1c[10]);
        float m1 = (part[b * 48 + 11] + part[b * 48 + 23])
                 + (part[b * 48 + 35] + part[b * 48 + 47]) + __ldg(&b1c[11]);
        int fl = (m0 >= m1) ? 1 : 0;
        e1[b] = fl;
        sflag = fl;
        if (fl) e2[b] = 0;     // deterministic; unused when e1 selected
    }
    __syncthreads();
    if (sflag) return;

    {
        const float* hb = h1 + (size_t)b * KP1P;
        for (int i = tid; i < 8450; i += 256) {
            int ic = i / 169, rem = i - ic * 169;
            int r = rem / 13, c = rem - r * 13;
            hs[ic * 182 + r * 14 + c] = hb[i];
        }
        for (int i = tid; i < 50; i += 256) bss[i] = bias[i];
        for (int i = tid; i < 1250; i += 256)
            ((float4*)wb)[i] = ((const float4*)wpk)[i];
    }
    __syncthreads();

    const int osub = tid / 25, pos = tid % 25;
    const int oc0 = osub * 5;
    const int py = pos / 5, px = pos % 5;
    const int Y = 2 * py, X = 2 * px;
    const bool active = (tid < 250);

    unsigned long long aT[5], aB[5];
    #pragma unroll
    for (int j = 0; j < 5; j++) { aT[j] = 0ULL; aB[j] = 0ULL; }

    for (int t = 0; t < 10; t++) {
        const int cur = t & 1;
        if (t + 1 < 10) {
            const float4* src = (const float4*)wpk + (t + 1) * 1250;
            float4* dst = (float4*)(wb + (cur ^ 1) * 2500);
            for (int i = tid; i < 1250; i += 256) dst[i] = src[i];
        }
        if (active) {
            #pragma unroll
            for (int i5 = 0; i5 < 5; i5++) {
                const float* hc = hs + (t * 5 + i5) * 182;
                unsigned long long P[4][3];
                #pragma unroll
                for (int r = 0; r < 4; r++) {
                    float2 v0 = *(const float2*)(hc + (Y + r) * 14 + X);
                    float2 v1 = *(const float2*)(hc + (Y + r) * 14 + X + 2);
                    asm("mov.b64 %0, {%1, %2};" : "=l"(P[r][0])
                        : "r"(__float_as_uint(v0.x)), "r"(__float_as_uint(v0.y)));
                    asm("mov.b64 %0, {%1, %2};" : "=l"(P[r][1])
                        : "r"(__float_as_uint(v0.y)), "r"(__float_as_uint(v1.x)));
                    asm("mov.b64 %0, {%1, %2};" : "=l"(P[r][2])
                        : "r"(__float_as_uint(v1.x)), "r"(__float_as_uint(v1.y)));
                }
                const float2* wrow = wb + cur * 2500 + (i5 * 50 + oc0) * 10;
                #pragma unroll
                for (int j = 0; j < 5; j++) {
                    const float2* wp = wrow + j * 10;
                    ulonglong2 q0 = *(const ulonglong2*)(wp);
                    ulonglong2 q1 = *(const ulonglong2*)(wp + 2);
                    ulonglong2 q2 = *(const ulonglong2*)(wp + 4);
                    ulonglong2 q3 = *(const ulonglong2*)(wp + 6);
                    unsigned long long w8 = *(const unsigned long long*)(wp + 8);
                    unsigned long long wv[9] = {q0.x, q0.y, q1.x, q1.y,
                                                q2.x, q2.y, q3.x, q3.y, w8};
                    #pragma unroll
                    for (int ky = 0; ky < 3; ky++)
                        #pragma unroll
                        for (int kx = 0; kx < 3; kx++) {
                            asm("fma.rn.f32x2 %0, %1, %2, %0;"
                                : "+l"(aT[j]) : "l"(P[ky][kx]), "l"(wv[ky * 3 + kx]));
                            asm("fma.rn.f32x2 %0, %1, %2, %0;"
                                : "+l"(aB[j]) : "l"(P[ky + 1][kx]), "l"(wv[ky * 3 + kx]));
                        }
                }
            }
        }
        __syncthreads();
    }

    float hd[12];
    #pragma unroll
    for (int jj = 0; jj < 12; jj++) hd[jj] = 0.f;
    if (active) {
        float v5[5];
        #pragma unroll
        for (int j = 0; j < 5; j++) {
            unsigned int u0, u1, u2, u3;
            asm("mov.b64 {%0, %1}, %2;" : "=r"(u0), "=r"(u1) : "l"(aT[j]));
            asm("mov.b64 {%0, %1}, %2;" : "=r"(u2), "=r"(u3) : "l"(aB[j]));
            float m = fmaxf(fmaxf(__uint_as_float(u0), __uint_as_float(u1)),
                            fmaxf(__uint_as_float(u2), __uint_as_float(u3)));
            m += bss[oc0 + j];
            v5[j] = fmaxf(m, 0.f);
            h2s[(oc0 + j) * 25 + pos] = v5[j];
        }
        #pragma unroll
        for (int jj = 0; jj < 12; jj++) {
            float s = 0.f;
            #pragma unroll
            for (int j = 0; j < 5; j++)
                s += v5[j] * __ldg(&W2[(size_t)jj * KP2P + (oc0 + j) * 25 + pos]);
            hd[jj] = s;
        }
    }
    const int lane = tid & 31, wrp = tid >> 5;
    #pragma unroll
    for (int jj = 0; jj < 12; jj++) {
        #pragma unroll
        for (int off = 16; off; off >>= 1)
            hd[jj] += __shfl_xor_sync(0xffffffffu, hd[jj], off);
    }
    if (lane == 0) {
        #pragma unroll
        for (int jj = 0; jj < 12; jj++) red[jj * 8 + wrp] = hd[jj];
    }
    __syncthreads();
    if (tid < 12) {
        float s = __ldg(&b2c[tid]);
        #pragma unroll
        for (int w = 0; w < 8; w++) s += red[tid * 8 + w];
        red[96 + tid] = s;
    }
    __syncthreads();

    const float em0 = red[96 + 10], em1 = red[96 + 11];
    if (tid == 0) e2[b] = (em0 >= em1) ? 1 : 0;
    if (tid < 10) o2[b * 10 + tid] = red[96 + tid];
    if (em0 >= em1) return;

    // ---- fused conv3: h2s (smem) -> f3 ----
    if (tid < 250) {
        const int oc2 = tid % 50, grp = tid / 50;
        const float* w3 = c3_w + oc2 * 450 + grp * 90;
        float a0 = 0.f, a1 = 0.f, a2 = 0.f, a3 = 0.f;
        #pragma unroll
        for (int i2 = 0; i2 < 10; i2++) {
            const float* hc = h2s + (grp * 10 + i2) * 25;
            #pragma unroll
            for (int ky = 0; ky < 3; ky++)
                #pragma unroll
                for (int kx = 0; kx < 3; kx++) {
                    float wv = __ldg(&w3[i2 * 9 + ky * 3 + kx]);
                    a0 += hc[ky * 5 + kx] * wv;
                    a1 += hc[ky * 5 + kx + 1] * wv;
                    a2 += hc[(ky + 1) * 5 + kx] * wv;
                    a3 += hc[(ky + 1) * 5 + kx + 1] * wv;
                }
        }
        float* r3 = red3 + grp * 200 + oc2 * 4;
        r3[0] = a0; r3[1] = a1; r3[2] = a2; r3[3] = a3;
    }
    __syncthreads();
    if (tid < 50) {
        float a0 = 0.f, a1 = 0.f, a2 = 0.f, a3 = 0.f;
        #pragma unroll
        for (int g = 0; g < 5; g++) {
            const float* r3 = red3 + g * 200 + tid * 4;
            a0 += r3[0]; a1 += r3[1]; a2 += r3[2]; a3 += r3[3];
        }
        float m = fmaxf(fmaxf(a0, a1), fmaxf(a2, a3)) + __ldg(&c3_b[tid]);
        f3[b * 50 + tid] = fmaxf(m, 0.f);
    }
}

// ==== stage3 + final fused ===================================================
#define S3_G 32
#define S3_SMEM ((25000 + 5000 + 500 + S3_G * 50 + S3_G * 500 + S3_G * 10) * 4)

__global__ __launch_bounds__(256) void stage3final_kernel(
    const float* __restrict__ f3,
    const float* __restrict__ l1w, const float* __restrict__ l1b,
    const float* __restrict__ l2w, const float* __restrict__ l2b,
    const int* __restrict__ e1, const int* __restrict__ e2,
    const float* __restrict__ part, const float* __restrict__ b1c,
    const float* __restrict__ o2, float* __restrict__ out, int bbase)
{
    extern __shared__ __align__(16) float sm[];
    float* w1  = sm;
    float* w2  = sm + 25000;
    float* b1  = sm + 30000;
    float* fs  = sm + 30500;
    float* hid = sm + 32100;
    float* o3s = sm + 48100;
    int tid = threadIdx.x;
    int b0 = bbase + blockIdx.x * S3_G;

    for (int i = tid; i < 25000; i += 256) w1[i] = l1w[i];
    for (int i = tid; i < 5000;  i += 256) w2[i] = l2w[i];
    for (int i = tid; i < 500;   i += 256) b1[i] = l1b[i];
    for (int i = tid; i < S3_G * 50; i += 256) fs[i] = f3[b0 * 50 + i];
    __syncthreads();

    for (int hh = tid; hh < S3_G * 500; hh += 256) {
        int s = hh / 500, j = hh - s * 500;
        float a = b1[j];
        const float* fr = fs + s * 50;
        const float* wr = w1 + j * 50;
        #pragma unroll 10
        for (int k = 0; k < 50; k++) a += fr[k] * wr[k];
        hid[hh] = fmaxf(a, 0.f);
    }
    __syncthreads();

    for (int oo = tid; oo < S3_G * 10; oo += 256) {
        int s = oo / 10, n = oo - s * 10;
        float a = __ldg(&l2b[n]);
        const float* hr = hid + s * 500;
        const float* wr = w2 + n * 500;
        #pragma unroll 4
        for (int j = 0; j < 500; j++) a += hr[j] * wr[j];
        o3s[s * 10 + n] = a;
    }
    __syncthreads();

    if (tid < S3_G) {
        int b = b0 + tid;
        float v[10];
        if (e1[b]) {
            #pragma unroll
            for (int j = 0; j < 10; j++)
                v[j] = (part[b * 48 + j] + part[b * 48 + 12 + j])
                     + (part[b * 48 + 24 + j] + part[b * 48 + 36 + j]) + __ldg(&b1c[j]);
        } else if (e2[b]) {
            #pragma unroll
            for (int j = 0; j < 10; j++) v[j] = o2[b * 10 + j];
        } else {
            #pragma unroll
            for (int j = 0; j < 10; j++) v[j] = o3s[tid * 10 + j];
        }
        float mx = -1e30f;
        #pragma unroll
        for (int j = 0; j < 10; j++) mx = fmaxf(mx, v[j]);
        float sum = 0.f;
        #pragma unroll
        for (int j = 0; j < 10; j++) sum += expf(v[j] - mx);
        float l = logf(sum);
        #pragma unroll
        for (int j = 0; j < 10; j++) out[b * 10 + j] = v[j] - mx - l;
    }
}

// ---------------- launch ----------------------------------------------------
extern "C" void kernel_launch(void* const* d_in, const int* in_sizes, int n_in,
                              void* d_out, int out_size)
{
    const float* x      = (const float*)d_in[0];
    const float* c1_w   = (const float*)d_in[1];
    const float* c1_b   = (const float*)d_in[2];
    const float* c2_w   = (const float*)d_in[3];
    const float* c2_b   = (const float*)d_in[4];
    const float* c3_w   = (const float*)d_in[5];
    const float* c3_b   = (const float*)d_in[6];
    const float* l1c1_w = (const float*)d_in[7];
    const float* l1c1_b = (const float*)d_in[8];
    const float* l2c1_w = (const float*)d_in[9];
    const float* l2c1_b = (const float*)d_in[10];
    const float* l1c2_w = (const float*)d_in[11];
    const float* l1c2_b = (const float*)d_in[12];
    const float* l2c2_w = (const float*)d_in[13];
    const float* l2c2_b = (const float*)d_in[14];
    const float* l1_w   = (const float*)d_in[15];
    const float* l1_b   = (const float*)d_in[16];
    const float* l2_w   = (const float*)d_in[17];
    const float* l2_b   = (const float*)d_in[18];
    const float* d1_w   = (const float*)d_in[19];
    const float* d1_b   = (const float*)d_in[20];
    const float* d2_w   = (const float*)d_in[21];
    const float* d2_b   = (const float*)d_in[22];
    float* out = (float*)d_out;

    float *h1, *f3, *o2, *W1, *W2, *b1c, *b2c, *part1;
    float2 *wpk2;
    int *e1, *e2;
    cudaGetSymbolAddress((void**)&h1,   g_h1);
    cudaGetSymbolAddress((void**)&f3,   g_f3);
    cudaGetSymbolAddress((void**)&o2,   g_o2);
    cudaGetSymbolAddress((void**)&e1,   g_e1);
    cudaGetSymbolAddress((void**)&e2,   g_e2);
    cudaGetSymbolAddress((void**)&W1,   g_W1);
    cudaGetSymbolAddress((void**)&W2,   g_W2);
    cudaGetSymbolAddress((void**)&b1c,  g_b1c);
    cudaGetSymbolAddress((void**)&b2c,  g_b2c);
    cudaGetSymbolAddress((void**)&part1, g_part1);
    cudaGetSymbolAddress((void**)&wpk2, g_wpk2);

    static cudaStream_t s2 = nullptr, s3 = nullptr;
    static cudaEvent_t evA = nullptr, evP = nullptr, evC = nullptr;
    static int attr_set = 0;
    if (!attr_set) {
        cudaFuncSetAttribute(stagehead_part_kernel,
                             cudaFuncAttributeMaxDynamicSharedMemorySize, SH_SMEM);
        cudaFuncSetAttribute(conv2_kernel,
                             cudaFuncAttributeMaxDynamicSharedMemorySize, C2_SMEM);
        cudaFuncSetAttribute(stage3final_kernel,
                             cudaFuncAttributeMaxDynamicSharedMemorySize, S3_SMEM);
        cudaStreamCreateWithFlags(&s2, cudaStreamNonBlocking);
        cudaStreamCreateWithFlags(&s3, cudaStreamNonBlocking);
        cudaEventCreateWithFlags(&evA, cudaEventDisableTiming);
        cudaEventCreateWithFlags(&evP, cudaEventDisableTiming);
        cudaEventCreateWithFlags(&evC, cudaEventDisableTiming);
        attr_set = 1;
    }

    // fork both side streams from main
    cudaEventRecord(evA, 0);
    cudaStreamWaitEvent(s2, evA, 0);
    cudaStreamWaitEvent(s3, evA, 0);

    // prep on s2
    prep_kernel<<<128, 256, 0, s2>>>(l1c1_w, l1c1_b, l2c1_w, l2c1_b,
                                     l1c2_w, l1c2_b, l2c2_w, l2c2_b,
                                     d1_w, d1_b, d2_w, d2_b, c2_w,
                                     W1, b1c, W2, b2c, wpk2);
    cudaEventRecord(evP, s2);

    // chain 0 on main (half 0), chain 1 on s3 (half 1)
    conv1_kernel<<<HALF, 192>>>(x, c1_w, c1_b, h1, 0);
    conv1_kernel<<<HALF, 192, 0, s3>>>(x, c1_w, c1_b, h1, HALF);

    cudaStreamWaitEvent(0, evP, 0);
    cudaStreamWaitEvent(s3, evP, 0);

    stagehead_part_kernel<<<dim3(HALF / 16, 4), 256, SH_SMEM>>>(h1, KP1P, W1, part1, 0);
    stagehead_part_kernel<<<dim3(HALF / 16, 4), 256, SH_SMEM, s3>>>(h1, KP1P, W1, part1, HALF);

    conv2_kernel<<<HALF, 256, C2_SMEM>>>(h1, wpk2, c2_b, part1, b1c,
                                         W2, b2c, c3_w, c3_b, e1, e2, o2, f3, 0);
    conv2_kernel<<<HALF, 256, C2_SMEM, s3>>>(h1, wpk2, c2_b, part1, b1c,
                                             W2, b2c, c3_w, c3_b, e1, e2, o2, f3, HALF);

    stage3final_kernel<<<HALF / S3_G, 256, S3_SMEM>>>(
        f3, l1_w, l1_b, l2_w, l2_b, e1, e2, part1, b1c, o2, out, 0);
    stage3final_kernel<<<HALF / S3_G, 256, S3_SMEM, s3>>>(
        f3, l1_w, l1_b, l2_w, l2_b, e1, e2, part1, b1c, o2, out, HALF);

    // join chain 1 back into main
    cudaEventRecord(evC, s3);
    cudaStreamWaitEvent(0, evC, 0);
}

// round 17
// speedup vs baseline: 1.8449x; 1.6464x over previous
#include <cuda_runtime.h>
#include <math.h>
#include <stdint.h>

#define BATCH 4096
#define HALF 2048
#define K1 8450
#define K2 1250
#define KP1P 8704          // h1 row pitch (17 * 512)
#define KP2P 1536          // W2 row pitch

// ---------------- scratch (device globals; zero-initialized) ---------------
__device__ float g_h1[(size_t)BATCH * KP1P];
__device__ float g_f3[BATCH * 50];
__device__ float g_o2[BATCH * 10];
__device__ int   g_e1[BATCH];
__device__ int   g_e2[BATCH];
__device__ float g_W1[12 * KP1P];    // rows 0-9: l2c1@l1c1; 10-11: d1_w
__device__ float g_W2[12 * KP2P];
__device__ float g_b1c[12];
__device__ float g_b2c[12];
__device__ float g_part1[BATCH * 48];  // [b][split(4)][12]
__device__ float2 g_wpk2[50 * 500];    // conv2 weights [ic][oc][10] dup, pad k=9 zero

// ================= merged prep kernel v2 (row-parallel combine) =============
// block = 64 k-columns x 4 row-groups of 125; partials reduced via smem
__device__ void combine_part(
    const float* __restrict__ l1, const float* __restrict__ b1,
    const float* __restrict__ l2, const float* __restrict__ b2,
    const float* __restrict__ dw, const float* __restrict__ db,
    int K, int Kp, float* __restrict__ W12, float* __restrict__ bc12,
    int blk, float* l2T, float* red)
{
    const int tid = threadIdx.x;
    const int kl = tid & 63, g = tid >> 6;
    const int k = blk * 64 + kl;

    for (int i = tid; i < 5000; i += 256) {
        int j = i / 500, r = i - j * 500;
        l2T[r * 12 + j] = l2[i];
    }
    for (int r = tid; r < 500; r += 256) { l2T[r * 12 + 10] = 0.f; l2T[r * 12 + 11] = 0.f; }
    __syncthreads();

    float acc[10];
    #pragma unroll
    for (int j = 0; j < 10; j++) acc[j] = 0.f;
    if (k < K) {
        const int r0 = g * 125, r1 = r0 + 125;
        #pragma unroll 5
        for (int r = r0; r < r1; r++) {
            float a = __ldg(&l1[(size_t)r * K + k]);
            float4 w0 = *(const float4*)&l2T[r * 12];
            float4 w1 = *(const float4*)&l2T[r * 12 + 4];
            float2 w2 = *(const float2*)&l2T[r * 12 + 8];
            acc[0] += a * w0.x; acc[1] += a * w0.y; acc[2] += a * w0.z; acc[3] += a * w0.w;
            acc[4] += a * w1.x; acc[5] += a * w1.y; acc[6] += a * w1.z; acc[7] += a * w1.w;
            acc[8] += a * w2.x; acc[9] += a * w2.y;
        }
    }
    #pragma unroll
    for (int j = 0; j < 10; j++) red[(g * 64 + kl) * 10 + j] = acc[j];
    __syncthreads();

    if (g == 0) {
        if (k < K) {
            #pragma unroll
            for (int j = 0; j < 10; j++) {
                float s = (red[kl * 10 + j] + red[(64 + kl) * 10 + j])
                        + (red[(128 + kl) * 10 + j] + red[(192 + kl) * 10 + j]);
                W12[(size_t)j * Kp + k] = s;
            }
            W12[(size_t)10 * Kp + k] = __ldg(&dw[k]);
            W12[(size_t)11 * Kp + k] = __ldg(&dw[K + k]);
        } else {
            #pragma unroll
            for (int j = 0; j < 12; j++) W12[(size_t)j * Kp + k] = 0.f;
        }
    }
    if (blk == 0) {
        if (tid < 10) {
            float a = b2[tid];
            for (int r = 0; r < 500; r++) a += l2[tid * 500 + r] * b1[r];
            bc12[tid] = a;
        } else if (tid < 12) {
            bc12[tid] = db[tid - 10];
        }
    }
}

// blocks: 0-135 combine1 | 136-159 combine2 | 160+ pack w2
__global__ __launch_bounds__(256) void prep_kernel(
    const float* l1c1_w, const float* l1c1_b, const float* l2c1_w, const float* l2c1_b,
    const float* l1c2_w, const float* l1c2_b, const float* l2c2_w, const float* l2c2_b,
    const float* d1_w, const float* d1_b, const float* d2_w, const float* d2_b,
    const float* c2_w,
    float* W1, float* b1c, float* W2, float* b2c, float2* wpk2)
{
    __shared__ __align__(16) float l2T[500 * 12];
    __shared__ __align__(16) float red[256 * 10];
    int bx = blockIdx.x, tid = threadIdx.x;
    if (bx < 136) {
        combine_part(l1c1_w, l1c1_b, l2c1_w, l2c1_b, d1_w, d1_b,
                     K1, KP1P, W1, b1c, bx, l2T, red);
    } else if (bx < 160) {
        combine_part(l1c2_w, l1c2_b, l2c2_w, l2c2_b, d2_w, d2_b,
                     K2, KP2P, W2, b2c, bx - 136, l2T, red);
    } else {
        int i = (bx - 160) * 256 + tid;
        if (i < 22500) {
            int oc = i / 450, r = i - oc * 450;
            int ic = r / 9, k = r - ic * 9;
            float v = c2_w[i];
            wpk2[ic * 500 + oc * 10 + k] = make_float2(v, v);   // pad k=9 stays zero
        }
    }
}

// ---------------- conv1: register patch + packed f32x2 ----------------------
__global__ __launch_bounds__(192) void conv1_kernel(
    const float* __restrict__ x, const float* __restrict__ w,
    const float* __restrict__ bias, float* __restrict__ h1, int bbase)
{
    int b = bbase + blockIdx.x;
    __shared__ __align__(16) float xs[784];
    __shared__ __align__(16) float2 ws[450];
    __shared__ __align__(16) float bs[50];
    int tid = threadIdx.x;
    {
        const float4* xb = (const float4*)(x + (size_t)b * 784);
        for (int i = tid; i < 196; i += 192) ((float4*)xs)[i] = xb[i];
        for (int i = tid; i < 450; i += 192) { float v = w[i]; ws[i] = make_float2(v, v); }
        for (int i = tid; i < 50;  i += 192) bs[i] = bias[i];
    }
    __syncthreads();
    if (tid >= 169) return;

    const int py = tid / 13, px = tid % 13;
    const int Y = 2 * py, X = 2 * px;
    float p[4][4];
    #pragma unroll
    for (int r = 0; r < 4; r++)
        #pragma unroll
        for (int c = 0; c < 4; c++) p[r][c] = xs[(Y + r) * 28 + X + c];
    unsigned long long P[4][3];
    #pragma unroll
    for (int r = 0; r < 4; r++)
        #pragma unroll
        for (int k = 0; k < 3; k++)
            asm("mov.b64 %0, {%1, %2};" : "=l"(P[r][k])
                : "r"(__float_as_uint(p[r][k])), "r"(__float_as_uint(p[r][k + 1])));

    float* hb = h1 + (size_t)b * KP1P + tid;
    for (int oc = 0; oc < 50; oc++) {
        unsigned long long aT = 0ULL, aB = 0ULL;
        #pragma unroll
        for (int ky = 0; ky < 3; ky++)
            #pragma unroll
            for (int kx = 0; kx < 3; kx++) {
                unsigned long long w2 = *(const unsigned long long*)&ws[oc * 9 + ky * 3 + kx];
                asm("fma.rn.f32x2 %0, %1, %2, %0;" : "+l"(aT) : "l"(P[ky][kx]), "l"(w2));
                asm("fma.rn.f32x2 %0, %1, %2, %0;" : "+l"(aB) : "l"(P[ky + 1][kx]), "l"(w2));
            }
        unsigned int u0, u1, u2, u3;
        asm("mov.b64 {%0, %1}, %2;" : "=r"(u0), "=r"(u1) : "l"(aT));
        asm("mov.b64 {%0, %1}, %2;" : "=r"(u2), "=r"(u3) : "l"(aB));
        float m = fmaxf(fmaxf(__uint_as_float(u0), __uint_as_float(u1)),
                        fmaxf(__uint_as_float(u2), __uint_as_float(u3)));
        m += bs[oc];
        hb[oc * 169] = fmaxf(m, 0.f);
    }
}

// ====== stagehead: smem weights double-buffered, 4 K-splits =================
#define SH_SMEM (2 * 12 * 512 * 4)     // 48 KB
__global__ __launch_bounds__(256, 3) void stagehead_part_kernel(
    const float* __restrict__ f, int Kp,
    const float* __restrict__ W12, float* __restrict__ part, int bbase)
{
    extern __shared__ __align__(16) float ws[];   // [2][12][512]
    const int tid = threadIdx.x, lane = tid & 31, wid = tid >> 5;
    const int b0 = bbase + blockIdx.x * 16;
    const int split = blockIdx.y;
    const int s0 = b0 + wid * 2, s1 = s0 + 1;
    const int cBeg = split ? (4 * split + 1) : 0;
    const int cEnd = 4 * split + 5;

    float acc0[12], acc1[12];
    #pragma unroll
    for (int j = 0; j < 12; j++) { acc0[j] = 0.f; acc1[j] = 0.f; }

    const float* f0p = f + (size_t)s0 * Kp;
    const float* f1p = f + (size_t)s1 * Kp;

    {
        const int c = cBeg;
        for (int i = tid; i < 1536; i += 256) {
            int j = i >> 7, k4 = (i & 127) * 4;
            *(float4*)&ws[j * 512 + k4] =
                *(const float4*)&W12[(size_t)j * Kp + c * 512 + k4];
        }
    }
    __syncthreads();

    for (int c = cBeg; c < cEnd; c++) {
        const int buf = (c - cBeg) & 1;
        if (c + 1 < cEnd) {
            const int nb = buf ^ 1;
            for (int i = tid; i < 1536; i += 256) {
                int j = i >> 7, k4 = (i & 127) * 4;
                *(float4*)&ws[nb * 6144 + j * 512 + k4] =
                    *(const float4*)&W12[(size_t)j * Kp + (c + 1) * 512 + k4];
            }
        }
        const int kc = c * 512;
        float4 A0[4], A1[4];
        #pragma unroll
        for (int it = 0; it < 4; it++) {
            A0[it] = *(const float4*)(f0p + kc + it * 128 + lane * 4);
            A1[it] = *(const float4*)(f1p + kc + it * 128 + lane * 4);
        }
        const float* wb = ws + buf * 6144;
        #pragma unroll
        for (int it = 0; it < 4; it++) {
            const int kk = it * 128 + lane * 4;
            float4 a0 = A0[it], a1 = A1[it];
            #pragma unroll
            for (int j = 0; j < 12; j++) {
                float4 w = *(const float4*)&wb[j * 512 + kk];
                acc0[j] = fmaf(a0.x, w.x, fmaf(a0.y, w.y, fmaf(a0.z, w.z, fmaf(a0.w, w.w, acc0[j]))));
                acc1[j] = fmaf(a1.x, w.x, fmaf(a1.y, w.y, fmaf(a1.z, w.z, fmaf(a1.w, w.w, acc1[j]))));
            }
        }
        __syncthreads();
    }

    #pragma unroll
    for (int j = 0; j < 12; j++) {
        #pragma unroll
        for (int off = 16; off; off >>= 1) {
            acc0[j] += __shfl_xor_sync(0xffffffffu, acc0[j], off);
            acc1[j] += __shfl_xor_sync(0xffffffffu, acc1[j], off);
        }
    }
    if (lane == 0) {
        #pragma unroll
        for (int j = 0; j < 12; j++) {
            part[s0 * 48 + split * 12 + j] = acc0[j];
            part[s1 * 48 + split * 12 + j] = acc1[j];
        }
    }
}

// ====== conv2 mega: conv2 + stage-2 head + conv3, double-buffered weights ===
#define C2_SMEM 86064
__global__ __launch_bounds__(256, 2) void conv2_kernel(
    const float* __restrict__ h1, const float2* __restrict__ wpk,
    const float* __restrict__ bias, const float* __restrict__ part,
    const float* __restrict__ b1c,
    const float* __restrict__ W2, const float* __restrict__ b2c,
    const float* __restrict__ c3_w, const float* __restrict__ c3_b,
    int* __restrict__ e1, int* __restrict__ e2,
    float* __restrict__ o2, float* __restrict__ f3, int bbase)
{
    extern __shared__ __align__(16) char csm[];
    float*  hs   = (float*)csm;
    float2* wb   = (float2*)(csm + 36416);
    float*  h2s  = (float*)(csm + 76416);
    float*  bss  = (float*)(csm + 81416);
    float*  red  = (float*)(csm + 81616);
    float*  red3 = (float*)(csm + 82064);
    __shared__ int sflag;

    const int b = bbase + blockIdx.x;
    const int tid = threadIdx.x;
    if (tid == 0) {
        float m0 = (part[b * 48 + 10] + part[b * 48 + 22])
                 + (part[b * 48 + 34] + part[b * 48 + 46]) + __ldg(&b1c[10]);
        float m1 = (part[b * 48 + 11] + part[b * 48 + 23])
                 + (part[b * 48 + 35] + part[b * 48 + 47]) + __ldg(&b1c[11]);
        int fl = (m0 >= m1) ? 1 : 0;
        e1[b] = fl;
        sflag = fl;
        if (fl) e2[b] = 0;     // deterministic; unused when e1 selected
    }
    __syncthreads();
    if (sflag) return;

    {
        const float* hb = h1 + (size_t)b * KP1P;
        for (int i = tid; i < 8450; i += 256) {
            int ic = i / 169, rem = i - ic * 169;
            int r = rem / 13, c = rem - r * 13;
            hs[ic * 182 + r * 14 + c] = hb[i];
        }
        for (int i = tid; i < 50; i += 256) bss[i] = bias[i];
        for (int i = tid; i < 1250; i += 256)
            ((float4*)wb)[i] = ((const float4*)wpk)[i];
    }
    __syncthreads();

    const int osub = tid / 25, pos = tid % 25;
    const int oc0 = osub * 5;
    const int py = pos / 5, px = pos % 5;
    const int Y = 2 * py, X = 2 * px;
    const bool active = (tid < 250);

    unsigned long long aT[5], aB[5];
    #pragma unroll
    for (int j = 0; j < 5; j++) { aT[j] = 0ULL; aB[j] = 0ULL; }

    for (int t = 0; t < 10; t++) {
        const int cur = t & 1;
        if (t + 1 < 10) {
            const float4* src = (const float4*)wpk + (t + 1) * 1250;
            float4* dst = (float4*)(wb + (cur ^ 1) * 2500);
            for (int i = tid; i < 1250; i += 256) dst[i] = src[i];
        }
        if (active) {
            #pragma unroll
            for (int i5 = 0; i5 < 5; i5++) {
                const float* hc = hs + (t * 5 + i5) * 182;
                unsigned long long P[4][3];
                #pragma unroll
                for (int r = 0; r < 4; r++) {
                    float2 v0 = *(const float2*)(hc + (Y + r) * 14 + X);
                    float2 v1 = *(const float2*)(hc + (Y + r) * 14 + X + 2);
                    asm("mov.b64 %0, {%1, %2};" : "=l"(P[r][0])
                        : "r"(__float_as_uint(v0.x)), "r"(__float_as_uint(v0.y)));
                    asm("mov.b64 %0, {%1, %2};" : "=l"(P[r][1])
                        : "r"(__float_as_uint(v0.y)), "r"(__float_as_uint(v1.x)));
                    asm("mov.b64 %0, {%1, %2};" : "=l"(P[r][2])
                        : "r"(__float_as_uint(v1.x)), "r"(__float_as_uint(v1.y)));
                }
                const float2* wrow = wb + cur * 2500 + (i5 * 50 + oc0) * 10;
                #pragma unroll
                for (int j = 0; j < 5; j++) {
                    const float2* wp = wrow + j * 10;
                    ulonglong2 q0 = *(const ulonglong2*)(wp);
                    ulonglong2 q1 = *(const ulonglong2*)(wp + 2);
                    ulonglong2 q2 = *(const ulonglong2*)(wp + 4);
                    ulonglong2 q3 = *(const ulonglong2*)(wp + 6);
                    unsigned long long w8 = *(const unsigned long long*)(wp + 8);
                    unsigned long long wv[9] = {q0.x, q0.y, q1.x, q1.y,
                                                q2.x, q2.y, q3.x, q3.y, w8};
                    #pragma unroll
                    for (int ky = 0; ky < 3; ky++)
                        #pragma unroll
                        for (int kx = 0; kx < 3; kx++) {
                            asm("fma.rn.f32x2 %0, %1, %2, %0;"
                                : "+l"(aT[j]) : "l"(P[ky][kx]), "l"(wv[ky * 3 + kx]));
                            asm("fma.rn.f32x2 %0, %1, %2, %0;"
                                : "+l"(aB[j]) : "l"(P[ky + 1][kx]), "l"(wv[ky * 3 + kx]));
                        }
                }
            }
        }
        __syncthreads();
    }

    float hd[12];
    #pragma unroll
    for (int jj = 0; jj < 12; jj++) hd[jj] = 0.f;
    if (active) {
        float v5[5];
        #pragma unroll
        for (int j = 0; j < 5; j++) {
            unsigned int u0, u1, u2, u3;
            asm("mov.b64 {%0, %1}, %2;" : "=r"(u0), "=r"(u1) : "l"(aT[j]));
            asm("mov.b64 {%0, %1}, %2;" : "=r"(u2), "=r"(u3) : "l"(aB[j]));
            float m = fmaxf(fmaxf(__uint_as_float(u0), __uint_as_float(u1)),
                            fmaxf(__uint_as_float(u2), __uint_as_float(u3)));
            m += bss[oc0 + j];
            v5[j] = fmaxf(m, 0.f);
            h2s[(oc0 + j) * 25 + pos] = v5[j];
        }
        #pragma unroll
        for (int jj = 0; jj < 12; jj++) {
            float s = 0.f;
            #pragma unroll
            for (int j = 0; j < 5; j++)
                s += v5[j] * __ldg(&W2[(size_t)jj * KP2P + (oc0 + j) * 25 + pos]);
            hd[jj] = s;
        }
    }
    const int lane = tid & 31, wrp = tid >> 5;
    #pragma unroll
    for (int jj = 0; jj < 12; jj++) {
        #pragma unroll
        for (int off = 16; off; off >>= 1)
            hd[jj] += __shfl_xor_sync(0xffffffffu, hd[jj], off);
    }
    if (lane == 0) {
        #pragma unroll
        for (int jj = 0; jj < 12; jj++) red[jj * 8 + wrp] = hd[jj];
    }
    __syncthreads();
    if (tid < 12) {
        float s = __ldg(&b2c[tid]);
        #pragma unroll
        for (int w = 0; w < 8; w++) s += red[tid * 8 + w];
        red[96 + tid] = s;
    }
    __syncthreads();

    const float em0 = red[96 + 10], em1 = red[96 + 11];
    if (tid == 0) e2[b] = (em0 >= em1) ? 1 : 0;
    if (tid < 10) o2[b * 10 + tid] = red[96 + tid];
    if (em0 >= em1) return;

    // ---- fused conv3: h2s (smem) -> f3 ----
    if (tid < 250) {
        const int oc2 = tid % 50, grp = tid / 50;
        const float* w3 = c3_w + oc2 * 450 + grp * 90;
        float a0 = 0.f, a1 = 0.f, a2 = 0.f, a3 = 0.f;
        #pragma unroll
        for (int i2 = 0; i2 < 10; i2++) {
            const float* hc = h2s + (grp * 10 + i2) * 25;
            #pragma unroll
            for (int ky = 0; ky < 3; ky++)
                #pragma unroll
                for (int kx = 0; kx < 3; kx++) {
                    float wv = __ldg(&w3[i2 * 9 + ky * 3 + kx]);
                    a0 += hc[ky * 5 + kx] * wv;
                    a1 += hc[ky * 5 + kx + 1] * wv;
                    a2 += hc[(ky + 1) * 5 + kx] * wv;
                    a3 += hc[(ky + 1) * 5 + kx + 1] * wv;
                }
        }
        float* r3 = red3 + grp * 200 + oc2 * 4;
        r3[0] = a0; r3[1] = a1; r3[2] = a2; r3[3] = a3;
    }
    __syncthreads();
    if (tid < 50) {
        float a0 = 0.f, a1 = 0.f, a2 = 0.f, a3 = 0.f;
        #pragma unroll
        for (int g = 0; g < 5; g++) {
            const float* r3 = red3 + g * 200 + tid * 4;
            a0 += r3[0]; a1 += r3[1]; a2 += r3[2]; a3 += r3[3];
        }
        float m = fmaxf(fmaxf(a0, a1), fmaxf(a2, a3)) + __ldg(&c3_b[tid]);
        f3[b * 50 + tid] = fmaxf(m, 0.f);
    }
}

// ==== stage3 + final fused ===================================================
#define S3_G 32
#define S3_SMEM ((25000 + 5000 + 500 + S3_G * 50 + S3_G * 500 + S3_G * 10) * 4)

__global__ __launch_bounds__(256) void stage3final_kernel(
    const float* __restrict__ f3,
    const float* __restrict__ l1w, const float* __restrict__ l1b,
    const float* __restrict__ l2w, const float* __restrict__ l2b,
    const int* __restrict__ e1, const int* __restrict__ e2,
    const float* __restrict__ part, const float* __restrict__ b1c,
    const float* __restrict__ o2, float* __restrict__ out, int bbase)
{
    extern __shared__ __align__(16) float sm[];
    float* w1  = sm;
    float* w2  = sm + 25000;
    float* b1  = sm + 30000;
    float* fs  = sm + 30500;
    float* hid = sm + 32100;
    float* o3s = sm + 48100;
    int tid = threadIdx.x;
    int b0 = bbase + blockIdx.x * S3_G;

    for (int i = tid; i < 25000; i += 256) w1[i] = l1w[i];
    for (int i = tid; i < 5000;  i += 256) w2[i] = l2w[i];
    for (int i = tid; i < 500;   i += 256) b1[i] = l1b[i];
    for (int i = tid; i < S3_G * 50; i += 256) fs[i] = f3[b0 * 50 + i];
    __syncthreads();

    for (int hh = tid; hh < S3_G * 500; hh += 256) {
        int s = hh / 500, j = hh - s * 500;
        float a = b1[j];
        const float* fr = fs + s * 50;
        const float* wr = w1 + j * 50;
        #pragma unroll 10
        for (int k = 0; k < 50; k++) a += fr[k] * wr[k];
        hid[hh] = fmaxf(a, 0.f);
    }
    __syncthreads();

    for (int oo = tid; oo < S3_G * 10; oo += 256) {
        int s = oo / 10, n = oo - s * 10;
        float a = __ldg(&l2b[n]);
        const float* hr = hid + s * 500;
        const float* wr = w2 + n * 500;
        #pragma unroll 4
        for (int j = 0; j < 500; j++) a += hr[j] * wr[j];
        o3s[s * 10 + n] = a;
    }
    __syncthreads();

    if (tid < S3_G) {
        int b = b0 + tid;
        float v[10];
        if (e1[b]) {
            #pragma unroll
            for (int j = 0; j < 10; j++)
                v[j] = (part[b * 48 + j] + part[b * 48 + 12 + j])
                     + (part[b * 48 + 24 + j] + part[b * 48 + 36 + j]) + __ldg(&b1c[j]);
        } else if (e2[b]) {
            #pragma unroll
            for (int j = 0; j < 10; j++) v[j] = o2[b * 10 + j];
        } else {
            #pragma unroll
            for (int j = 0; j < 10; j++) v[j] = o3s[tid * 10 + j];
        }
        float mx = -1e30f;
        #pragma unroll
        for (int j = 0; j < 10; j++) mx = fmaxf(mx, v[j]);
        float sum = 0.f;
        #pragma unroll
        for (int j = 0; j < 10; j++) sum += expf(v[j] - mx);
        float l = logf(sum);
        #pragma unroll
        for (int j = 0; j < 10; j++) out[b * 10 + j] = v[j] - mx - l;
    }
}

// ---------------- launch ----------------------------------------------------
extern "C" void kernel_launch(void* const* d_in, const int* in_sizes, int n_in,
                              void* d_out, int out_size)
{
    const float* x      = (const float*)d_in[0];
    const float* c1_w   = (const float*)d_in[1];
    const float* c1_b   = (const float*)d_in[2];
    const float* c2_w   = (const float*)d_in[3];
    const float* c2_b   = (const float*)d_in[4];
    const float* c3_w   = (const float*)d_in[5];
    const float* c3_b   = (const float*)d_in[6];
    const float* l1c1_w = (const float*)d_in[7];
    const float* l1c1_b = (const float*)d_in[8];
    const float* l2c1_w = (const float*)d_in[9];
    const float* l2c1_b = (const float*)d_in[10];
    const float* l1c2_w = (const float*)d_in[11];
    const float* l1c2_b = (const float*)d_in[12];
    const float* l2c2_w = (const float*)d_in[13];
    const float* l2c2_b = (const float*)d_in[14];
    const float* l1_w   = (const float*)d_in[15];
    const float* l1_b   = (const float*)d_in[16];
    const float* l2_w   = (const float*)d_in[17];
    const float* l2_b   = (const float*)d_in[18];
    const float* d1_w   = (const float*)d_in[19];
    const float* d1_b   = (const float*)d_in[20];
    const float* d2_w   = (const float*)d_in[21];
    const float* d2_b   = (const float*)d_in[22];
    float* out = (float*)d_out;

    float *h1, *f3, *o2, *W1, *W2, *b1c, *b2c, *part1;
    float2 *wpk2;
    int *e1, *e2;
    cudaGetSymbolAddress((void**)&h1,   g_h1);
    cudaGetSymbolAddress((void**)&f3,   g_f3);
    cudaGetSymbolAddress((void**)&o2,   g_o2);
    cudaGetSymbolAddress((void**)&e1,   g_e1);
    cudaGetSymbolAddress((void**)&e2,   g_e2);
    cudaGetSymbolAddress((void**)&W1,   g_W1);
    cudaGetSymbolAddress((void**)&W2,   g_W2);
    cudaGetSymbolAddress((void**)&b1c,  g_b1c);
    cudaGetSymbolAddress((void**)&b2c,  g_b2c);
    cudaGetSymbolAddress((void**)&part1, g_part1);
    cudaGetSymbolAddress((void**)&wpk2, g_wpk2);

    static cudaStream_t s2 = nullptr, s3 = nullptr;
    static cudaEvent_t evA = nullptr, evP = nullptr, evC = nullptr;
    static int attr_set = 0;
    if (!attr_set) {
        cudaFuncSetAttribute(stagehead_part_kernel,
                             cudaFuncAttributeMaxDynamicSharedMemorySize, SH_SMEM);
        cudaFuncSetAttribute(conv2_kernel,
                             cudaFuncAttributeMaxDynamicSharedMemorySize, C2_SMEM);
        cudaFuncSetAttribute(stage3final_kernel,
                             cudaFuncAttributeMaxDynamicSharedMemorySize, S3_SMEM);
        cudaStreamCreateWithFlags(&s2, cudaStreamNonBlocking);
        cudaStreamCreateWithFlags(&s3, cudaStreamNonBlocking);
        cudaEventCreateWithFlags(&evA, cudaEventDisableTiming);
        cudaEventCreateWithFlags(&evP, cudaEventDisableTiming);
        cudaEventCreateWithFlags(&evC, cudaEventDisableTiming);
        attr_set = 1;
    }

    // fork both side streams from main
    cudaEventRecord(evA, 0);
    cudaStreamWaitEvent(s2, evA, 0);
    cudaStreamWaitEvent(s3, evA, 0);

    // prep on s2 (row-parallel combine: 136 + 24 + 88 blocks)
    prep_kernel<<<248, 256, 0, s2>>>(l1c1_w, l1c1_b, l2c1_w, l2c1_b,
                                     l1c2_w, l1c2_b, l2c2_w, l2c2_b,
                                     d1_w, d1_b, d2_w, d2_b, c2_w,
                                     W1, b1c, W2, b2c, wpk2);
    cudaEventRecord(evP, s2);

    // chain 0 on main (half 0), chain 1 on s3 (half 1)
    conv1_kernel<<<HALF, 192>>>(x, c1_w, c1_b, h1, 0);
    conv1_kernel<<<HALF, 192, 0, s3>>>(x, c1_w, c1_b, h1, HALF);

    cudaStreamWaitEvent(0, evP, 0);
    cudaStreamWaitEvent(s3, evP, 0);

    stagehead_part_kernel<<<dim3(HALF / 16, 4), 256, SH_SMEM>>>(h1, KP1P, W1, part1, 0);
    stagehead_part_kernel<<<dim3(HALF / 16, 4), 256, SH_SMEM, s3>>>(h1, KP1P, W1, part1, HALF);

    conv2_kernel<<<HALF, 256, C2_SMEM>>>(h1, wpk2, c2_b, part1, b1c,
                                         W2, b2c, c3_w, c3_b, e1, e2, o2, f3, 0);
    conv2_kernel<<<HALF, 256, C2_SMEM, s3>>>(h1, wpk2, c2_b, part1, b1c,
                                             W2, b2c, c3_w, c3_b, e1, e2, o2, f3, HALF);

    stage3final_kernel<<<HALF / S3_G, 256, S3_SMEM>>>(
        f3, l1_w, l1_b, l2_w, l2_b, e1, e2, part1, b1c, o2, out, 0);
    stage3final_kernel<<<HALF / S3_G, 256, S3_SMEM, s3>>>(
        f3, l1_w, l1_b, l2_w, l2_b, e1, e2, part1, b1c, o2, out, HALF);

    // join chain 1 back into main
    cudaEventRecord(evC, s3);
    cudaStreamWaitEvent(0, evC, 0);
}